// round 12
// baseline (speedup 1.0000x reference)
#include <cuda_runtime.h>
#include <cstdint>

// 2-layer GCN, N=100000, E=3200000, 384 -> 128 -> 64.
// m' = x@W (unscaled tf32 tensor-core GEMM); acc[n] = dis[n]*m'[n] + sum dis[s]*m'[s];
// out = act(dis[n]*acc + b). CSR build forked to side stream.
// GEMMs use fragment-packed smem layouts: one LDS.128 per A-frag, one LDS.64
// per B-frag (R11 profile showed L1=45% / tensor=23% => LDS-bound).
// All __device__ buffers via cudaGetSymbolAddress (GB300/ATS host-shadow trap).

#define NN 100000
#define EE 3200000
#define SCAN_BLOCKS 98   // ceil(100000/1024)

__device__ int   g_hist[NN];
__device__ int   g_row_ptr[NN + 1];
__device__ int   g_cursor[NN];
__device__ int   g_part[SCAN_BLOCKS];
__device__ int   g_eidx[EE];
__device__ float g_dis[NN];
__device__ __align__(16) float g_m1[NN * 128];
__device__ __align__(16) float g_h1[NN * 128];
__device__ __align__(16) float g_m2[NN * 64];

namespace {
cudaStream_t g_side = nullptr;
cudaEvent_t  g_ev_fork = nullptr, g_ev_join = nullptr;
struct Init {
    Init() {
        if (cudaStreamCreateWithFlags(&g_side, cudaStreamNonBlocking) != cudaSuccess)
            g_side = nullptr;
        if (cudaEventCreateWithFlags(&g_ev_fork, cudaEventDisableTiming) != cudaSuccess)
            g_ev_fork = nullptr;
        if (cudaEventCreateWithFlags(&g_ev_join, cudaEventDisableTiming) != cudaSuccess)
            g_ev_join = nullptr;
    }
};
static Init s_init;
}

// ---------------------------------------------------------------------------
// CSR build
// ---------------------------------------------------------------------------
__global__ void zero_hist_kernel(int* __restrict__ hist) {
    int i = blockIdx.x * 256 + threadIdx.x;
    if (i < NN) hist[i] = 0;
}

__global__ void hist_kernel(const int* __restrict__ dst, int* __restrict__ hist) {
    int e = blockIdx.x * 256 + threadIdx.x;
    if (e < EE) atomicAdd(&hist[dst[e]], 1);
}

__global__ void scan1_kernel(const int* __restrict__ hist, int* __restrict__ row_ptr,
                             int* __restrict__ part)
{
    int gi = blockIdx.x * 1024 + threadIdx.x;
    int v = (gi < NN) ? hist[gi] : 0;
    int lane = threadIdx.x & 31, wid = threadIdx.x >> 5;

    int x = v;
#pragma unroll
    for (int o = 1; o < 32; o <<= 1) {
        int t = __shfl_up_sync(0xffffffffu, x, o);
        if (lane >= o) x += t;
    }
    __shared__ int wsum[32];
    if (lane == 31) wsum[wid] = x;
    __syncthreads();
    if (wid == 0) {
        int y = wsum[lane];
#pragma unroll
        for (int o = 1; o < 32; o <<= 1) {
            int t = __shfl_up_sync(0xffffffffu, y, o);
            if (lane >= o) y += t;
        }
        wsum[lane] = y;
    }
    __syncthreads();
    int incl = x + (wid ? wsum[wid - 1] : 0);
    if (gi < NN) row_ptr[gi] = incl - v;
    if (threadIdx.x == 1023) part[blockIdx.x] = incl;
}

__global__ void scan2_kernel(int* __restrict__ part, int* __restrict__ row_ptr)
{
    int lane = threadIdx.x & 31, wid = threadIdx.x >> 5;
    int v = (threadIdx.x < SCAN_BLOCKS) ? part[threadIdx.x] : 0;
    int x = v;
#pragma unroll
    for (int o = 1; o < 32; o <<= 1) {
        int t = __shfl_up_sync(0xffffffffu, x, o);
        if (lane >= o) x += t;
    }
    __shared__ int ws[4];
    if (lane == 31) ws[wid] = x;
    __syncthreads();
    int add = 0;
    for (int w = 0; w < wid; w++) add += ws[w];
    int incl = x + add;
    if (threadIdx.x < SCAN_BLOCKS) part[threadIdx.x] = incl - v;
    if (threadIdx.x == SCAN_BLOCKS - 1) row_ptr[NN] = incl;
}

__global__ void scan3_kernel(int* __restrict__ row_ptr, const int* __restrict__ part,
                             const int* __restrict__ hist, int* __restrict__ cursor,
                             float* __restrict__ dis)
{
    int i = blockIdx.x * 1024 + threadIdx.x;
    if (i < NN) {
        int rp = row_ptr[i] + part[blockIdx.x];
        row_ptr[i] = rp;
        cursor[i] = rp;
        dis[i] = rsqrtf((float)(hist[i] + 1));
    }
}

__global__ void place_kernel(const int* __restrict__ src, const int* __restrict__ dst,
                             int* __restrict__ cursor, int* __restrict__ eidx) {
    int e = blockIdx.x * 256 + threadIdx.x;
    if (e >= EE) return;
    int d = dst[e];
    int slot = atomicAdd(&cursor[d], 1);
    eidx[slot] = src[e];
}

// ---------------------------------------------------------------------------
// TF32 tensor-core GEMM with fragment-packed smem.
// m = A @ W. A [M,K] row-major, W [K,BN] row-major, output N == BN.
// Block 128 x BN x 16, 256 threads = 8 warps (4m x 2n), warp tile 32 x BN/2.
// As2: float4[(ks,mf,gID,tig)] = {A(g,t), A(g+8,t), A(g,t+4), A(g+8,t+4)}
// Bs2: float2[(ks,nf,gID,tig)] = {B(t,n), B(t+4,n)}
// ---------------------------------------------------------------------------
__device__ __forceinline__ float f2tf32(float x) {
    uint32_t u;
    asm("cvt.rna.tf32.f32 %0, %1;" : "=r"(u) : "f"(x));
    return __uint_as_float(u);
}

template<int BN>
__global__ __launch_bounds__(256)
void gemm_tf32_kernel(const float* __restrict__ A, const float* __restrict__ W,
                      float* __restrict__ m, int M, int K)
{
    constexpr int BM = 128, BK = 16;
    constexpr int NFRAG = BN / 16;             // n-frags per warp
    constexpr int AF4 = BM * BK / 4;           // 512
    constexpr int BF4 = BK * BN / 4;           // 512 (BN=128) / 256 (BN=64)
    constexpr int APT = AF4 / 256;             // 2
    constexpr int BPT = (BF4 + 255) / 256;     // 2 / 1

    __shared__ float4 As2[2 * 8 * 8 * 4];          // 512 f4 = 8KB
    __shared__ float2 Bs2[2 * (BN / 8) * 8 * 4];   // 8KB / 4KB

    const int tid = threadIdx.x;
    const int wid = tid >> 5, lane = tid & 31;
    const int gID = lane >> 2;                 // 0..7
    const int tig = lane & 3;                  // 0..3
    const int wm = (wid & 3) * 32;
    const int wn = (wid >> 2) * (BN / 2);
    const int row0 = blockIdx.x * BM;

    float c[2][NFRAG][4];
#pragma unroll
    for (int i = 0; i < 2; i++)
#pragma unroll
        for (int j = 0; j < NFRAG; j++)
#pragma unroll
            for (int q = 0; q < 4; q++) c[i][j][q] = 0.0f;

    float4 pa[APT], pb[BPT];

    auto loadA = [&](int kt) {
#pragma unroll
        for (int p = 0; p < APT; p++) {
            int i = tid + p * 256;
            int r  = i >> 2;
            int kc = (i & 3) * 4;
            int gr = row0 + r;
            pa[p] = (gr < M) ? *(const float4*)(A + (size_t)gr * K + kt + kc)
                             : make_float4(0.f, 0.f, 0.f, 0.f);
        }
    };
    auto loadB = [&](int kt) {
#pragma unroll
        for (int p = 0; p < BPT; p++) {
            int i = tid + p * 256;
            if (i < BF4) {
                int r  = i / (BN / 4);
                int cc = (i % (BN / 4)) * 4;
                pb[p] = *(const float4*)(W + (size_t)(kt + r) * BN + cc);
            }
        }
    };
    auto storeAB = [&]() {
        float* fa = (float*)As2;
#pragma unroll
        for (int p = 0; p < APT; p++) {
            int i = tid + p * 256;
            int r  = i >> 2;
            int kc = (i & 3) * 4;
            int ks = kc >> 3;
            int khalf = (kc >> 2) & 1;
            int mf = r >> 4;
            int mrem = r & 15;
            int g = mrem & 7;
            int mhalf = mrem >> 3;
            int comp = mhalf + 2 * khalf;
            // entries for tig = 0..3 are consecutive; 4 floats per entry
            int base = (((ks * 8 + mf) * 8 + g) * 4) * 4 + comp;
            fa[base +  0] = f2tf32(pa[p].x);   // k -> tig 0
            fa[base +  4] = f2tf32(pa[p].y);   // tig 1
            fa[base +  8] = f2tf32(pa[p].z);   // tig 2
            fa[base + 12] = f2tf32(pa[p].w);   // tig 3
        }
        float* fb = (float*)Bs2;
#pragma unroll
        for (int p = 0; p < BPT; p++) {
            int i = tid + p * 256;
            if (i < BF4) {
                int r  = i / (BN / 4);          // k row
                int cc = (i % (BN / 4)) * 4;    // n base
                int ks = r >> 3;
                int krem = r & 7;
                int tg = krem & 3;
                int khalf = krem >> 2;
                float v[4] = {f2tf32(pb[p].x), f2tf32(pb[p].y),
                              f2tf32(pb[p].z), f2tf32(pb[p].w)};
#pragma unroll
                for (int q = 0; q < 4; q++) {
                    int n = cc + q;
                    int nf = n >> 3;
                    int g = n & 7;
                    int idx = (((ks * (BN / 8) + nf) * 8 + g) * 4 + tg) * 2 + khalf;
                    fb[idx] = v[q];
                }
            }
        }
    };

    auto compute = [&]() {
#pragma unroll
        for (int ks = 0; ks < 2; ks++) {
            float4 av[2];
#pragma unroll
            for (int i = 0; i < 2; i++) {
                int mf = (wm >> 4) + i;
                av[i] = As2[((ks * 8 + mf) * 8 + gID) * 4 + tig];
            }
            float2 bv[NFRAG];
#pragma unroll
            for (int j = 0; j < NFRAG; j++) {
                int nf = (wn >> 3) + j;
                bv[j] = Bs2[((ks * (BN / 8) + nf) * 8 + gID) * 4 + tig];
            }
#pragma unroll
            for (int i = 0; i < 2; i++)
#pragma unroll
                for (int j = 0; j < NFRAG; j++) {
                    asm volatile(
                        "mma.sync.aligned.m16n8k8.row.col.f32.tf32.tf32.f32 "
                        "{%0,%1,%2,%3}, {%4,%5,%6,%7}, {%8,%9}, {%0,%1,%2,%3};"
                        : "+f"(c[i][j][0]), "+f"(c[i][j][1]),
                          "+f"(c[i][j][2]), "+f"(c[i][j][3])
                        : "r"(__float_as_uint(av[i].x)), "r"(__float_as_uint(av[i].y)),
                          "r"(__float_as_uint(av[i].z)), "r"(__float_as_uint(av[i].w)),
                          "r"(__float_as_uint(bv[j].x)), "r"(__float_as_uint(bv[j].y)));
                }
        }
    };

    loadA(0); loadB(0);
    storeAB();
    __syncthreads();

    for (int kt = BK; kt < K; kt += BK) {
        loadA(kt); loadB(kt);
        compute();
        __syncthreads();
        storeAB();
        __syncthreads();
    }
    compute();

#pragma unroll
    for (int i = 0; i < 2; i++) {
#pragma unroll
        for (int j = 0; j < NFRAG; j++) {
            int gcol = wn + j * 8 + 2 * tig;
            int grow0 = row0 + wm + i * 16 + gID;
            if (grow0 < M)
                *(float2*)(m + (size_t)grow0 * BN + gcol) =
                    make_float2(c[i][j][0], c[i][j][1]);
            int grow1 = grow0 + 8;
            if (grow1 < M)
                *(float2*)(m + (size_t)grow1 * BN + gcol) =
                    make_float2(c[i][j][2], c[i][j][3]);
        }
    }
}

// ---------------------------------------------------------------------------
// Gather aggregation, warp per node, dis applied at gather time.
// ---------------------------------------------------------------------------
__global__ __launch_bounds__(256)
void gather1_kernel(const float* __restrict__ m1, float* __restrict__ h1,
                    const int* __restrict__ row_ptr, const int* __restrict__ eidx,
                    const float* __restrict__ dis, const float* __restrict__ b1)
{
    int n = blockIdx.x * 8 + (threadIdx.x >> 5);
    if (n >= NN) return;
    int lane = threadIdx.x & 31;

    int start = row_ptr[n];
    int end   = row_ptr[n + 1];
    float dn = dis[n];

    float4 mv = *(const float4*)(m1 + (size_t)n * 128 + lane * 4);
    float4 acc;
    acc.x = dn * mv.x; acc.y = dn * mv.y; acc.z = dn * mv.z; acc.w = dn * mv.w;

    int e = start;
    for (; e + 4 <= end; e += 4) {
        int s0 = __ldg(eidx + e);
        int s1 = __ldg(eidx + e + 1);
        int s2 = __ldg(eidx + e + 2);
        int s3 = __ldg(eidx + e + 3);
        float d0 = __ldg(dis + s0), d1 = __ldg(dis + s1);
        float d2 = __ldg(dis + s2), d3 = __ldg(dis + s3);
        float4 v0 = *(const float4*)(m1 + (size_t)s0 * 128 + lane * 4);
        float4 v1 = *(const float4*)(m1 + (size_t)s1 * 128 + lane * 4);
        float4 v2 = *(const float4*)(m1 + (size_t)s2 * 128 + lane * 4);
        float4 v3 = *(const float4*)(m1 + (size_t)s3 * 128 + lane * 4);
        acc.x = fmaf(d0, v0.x, fmaf(d1, v1.x, fmaf(d2, v2.x, fmaf(d3, v3.x, acc.x))));
        acc.y = fmaf(d0, v0.y, fmaf(d1, v1.y, fmaf(d2, v2.y, fmaf(d3, v3.y, acc.y))));
        acc.z = fmaf(d0, v0.z, fmaf(d1, v1.z, fmaf(d2, v2.z, fmaf(d3, v3.z, acc.z))));
        acc.w = fmaf(d0, v0.w, fmaf(d1, v1.w, fmaf(d2, v2.w, fmaf(d3, v3.w, acc.w))));
    }
    for (; e < end; e++) {
        int s0 = __ldg(eidx + e);
        float d0 = __ldg(dis + s0);
        float4 v0 = *(const float4*)(m1 + (size_t)s0 * 128 + lane * 4);
        acc.x = fmaf(d0, v0.x, acc.x);
        acc.y = fmaf(d0, v0.y, acc.y);
        acc.z = fmaf(d0, v0.z, acc.z);
        acc.w = fmaf(d0, v0.w, acc.w);
    }

    float4 b = *(const float4*)(b1 + lane * 4);
    float4 o;
    o.x = fmaxf(fmaf(acc.x, dn, b.x), 0.f);
    o.y = fmaxf(fmaf(acc.y, dn, b.y), 0.f);
    o.z = fmaxf(fmaf(acc.z, dn, b.z), 0.f);
    o.w = fmaxf(fmaf(acc.w, dn, b.w), 0.f);
    *(float4*)(h1 + (size_t)n * 128 + lane * 4) = o;
}

__global__ __launch_bounds__(256)
void gather2_kernel(const float* __restrict__ m2, float* __restrict__ out,
                    const int* __restrict__ row_ptr, const int* __restrict__ eidx,
                    const float* __restrict__ dis, const float* __restrict__ b2)
{
    int n = blockIdx.x * 8 + (threadIdx.x >> 5);
    if (n >= NN) return;
    int lane = threadIdx.x & 31;

    int start = row_ptr[n];
    int end   = row_ptr[n + 1];
    float dn = dis[n];

    float2 mv = *(const float2*)(m2 + (size_t)n * 64 + lane * 2);
    float2 acc;
    acc.x = dn * mv.x; acc.y = dn * mv.y;

    int e = start;
    for (; e + 4 <= end; e += 4) {
        int s0 = __ldg(eidx + e);
        int s1 = __ldg(eidx + e + 1);
        int s2 = __ldg(eidx + e + 2);
        int s3 = __ldg(eidx + e + 3);
        float d0 = __ldg(dis + s0), d1 = __ldg(dis + s1);
        float d2 = __ldg(dis + s2), d3 = __ldg(dis + s3);
        float2 v0 = *(const float2*)(m2 + (size_t)s0 * 64 + lane * 2);
        float2 v1 = *(const float2*)(m2 + (size_t)s1 * 64 + lane * 2);
        float2 v2 = *(const float2*)(m2 + (size_t)s2 * 64 + lane * 2);
        float2 v3 = *(const float2*)(m2 + (size_t)s3 * 64 + lane * 2);
        acc.x = fmaf(d0, v0.x, fmaf(d1, v1.x, fmaf(d2, v2.x, fmaf(d3, v3.x, acc.x))));
        acc.y = fmaf(d0, v0.y, fmaf(d1, v1.y, fmaf(d2, v2.y, fmaf(d3, v3.y, acc.y))));
    }
    for (; e < end; e++) {
        int s0 = __ldg(eidx + e);
        float d0 = __ldg(dis + s0);
        float2 v0 = *(const float2*)(m2 + (size_t)s0 * 64 + lane * 2);
        acc.x = fmaf(d0, v0.x, acc.x);
        acc.y = fmaf(d0, v0.y, acc.y);
    }

    float2 b = *(const float2*)(b2 + lane * 2);
    float2 o;
    o.x = fmaf(acc.x, dn, b.x);
    o.y = fmaf(acc.y, dn, b.y);
    *(float2*)(out + (size_t)n * 64 + lane * 2) = o;
}

// ---------------------------------------------------------------------------
extern "C" void kernel_launch(void* const* d_in, const int* in_sizes, int n_in,
                              void* d_out, int out_size)
{
    void *pv;
    cudaGetSymbolAddress(&pv, g_hist);    int*   hist    = (int*)pv;
    cudaGetSymbolAddress(&pv, g_row_ptr); int*   row_ptr = (int*)pv;
    cudaGetSymbolAddress(&pv, g_cursor);  int*   cursor  = (int*)pv;
    cudaGetSymbolAddress(&pv, g_part);    int*   part    = (int*)pv;
    cudaGetSymbolAddress(&pv, g_eidx);    int*   eidx    = (int*)pv;
    cudaGetSymbolAddress(&pv, g_dis);     float* dis     = (float*)pv;
    cudaGetSymbolAddress(&pv, g_m1);      float* m1      = (float*)pv;
    cudaGetSymbolAddress(&pv, g_h1);      float* h1      = (float*)pv;
    cudaGetSymbolAddress(&pv, g_m2);      float* m2      = (float*)pv;

    const long long elems[6] = {38400000LL, 49152LL, 128LL, 8192LL, 64LL, 6400000LL};
    const long long bytesz[6] = {38400000LL*4, 49152LL*4, 128LL*4, 8192LL*4, 64LL*4, 6400000LL*4};
    const void* ptr[6] = {nullptr,nullptr,nullptr,nullptr,nullptr,nullptr};

    int matched = 0;
    for (int i = 0; i < n_in && i < 16; i++)
        for (int j = 0; j < 6; j++)
            if ((long long)in_sizes[i] == elems[j] && !ptr[j]) { ptr[j] = d_in[i]; matched++; break; }
    if (matched < 6) {
        for (int j = 0; j < 6; j++) ptr[j] = nullptr;
        matched = 0;
        for (int i = 0; i < n_in && i < 16; i++)
            for (int j = 0; j < 6; j++)
                if ((long long)in_sizes[i] == bytesz[j] && !ptr[j]) { ptr[j] = d_in[i]; matched++; break; }
    }
    if (matched < 6 && n_in >= 6)
        for (int j = 0; j < 6; j++) ptr[j] = d_in[j];

    const float* x  = (const float*)ptr[0];
    const float* W1 = (const float*)ptr[1];
    const float* b1 = (const float*)ptr[2];
    const float* W2 = (const float*)ptr[3];
    const float* b2 = (const float*)ptr[4];
    const int*   ei = (const int*)  ptr[5];
    const int* src = ei;
    const int* dst = ei + EE;
    float* out = (float*)d_out;

    const bool fork = (g_side && g_ev_fork && g_ev_join);
    cudaStream_t s_csr = fork ? g_side : (cudaStream_t)0;

    if (fork) {
        cudaEventRecord(g_ev_fork, 0);
        cudaStreamWaitEvent(g_side, g_ev_fork, 0);
    }

    // CSR build on side stream; gemm1 is the 4th launch (profiler slot).
    zero_hist_kernel<<<(NN + 255) / 256, 256, 0, s_csr>>>(hist);
    hist_kernel     <<<(EE + 255) / 256, 256, 0, s_csr>>>(dst, hist);
    scan1_kernel    <<<SCAN_BLOCKS, 1024, 0, s_csr>>>(hist, row_ptr, part);

    gemm_tf32_kernel<128><<<(NN + 127) / 128, 256>>>(x, W1, m1, NN, 384);

    scan2_kernel    <<<1, 128, 0, s_csr>>>(part, row_ptr);
    scan3_kernel    <<<SCAN_BLOCKS, 1024, 0, s_csr>>>(row_ptr, part, hist, cursor, dis);
    place_kernel    <<<(EE + 255) / 256, 256, 0, s_csr>>>(src, dst, cursor, eidx);
    if (fork) cudaEventRecord(g_ev_join, g_side);

    if (fork) cudaStreamWaitEvent((cudaStream_t)0, g_ev_join, 0);

    gather1_kernel<<<(NN + 7) / 8, 256>>>(m1, h1, row_ptr, eidx, dis, b1);

    gemm_tf32_kernel<64><<<(NN + 127) / 128, 256>>>(h1, W2, m2, NN, 128);

    gather2_kernel<<<(NN + 7) / 8, 256>>>(m2, out, row_ptr, eidx, dis, b2);
}

// round 13
// speedup vs baseline: 1.5119x; 1.5119x over previous
#include <cuda_runtime.h>
#include <cstdint>

// 2-layer GCN, N=100000, E=3200000, 384 -> 128 -> 64.
// m' = x@W (tf32 tensor-core GEMM, double-buffered smem); gather applies dis.
// R12 lesson: fragment-repacked smem exploded STS conflicts — reverted to the
// R11 layout (vectorized STS, scalar LDS) + 2-stage pipeline (1 barrier/tile).
// All __device__ buffers via cudaGetSymbolAddress (GB300/ATS host-shadow trap).

#define NN 100000
#define EE 3200000
#define SCAN_BLOCKS 98   // ceil(100000/1024)

__device__ int   g_hist[NN];
__device__ int   g_row_ptr[NN + 1];
__device__ int   g_cursor[NN];
__device__ int   g_part[SCAN_BLOCKS];
__device__ int   g_eidx[EE];
__device__ float g_dis[NN];
__device__ __align__(16) float g_m1[NN * 128];
__device__ __align__(16) float g_h1[NN * 128];
__device__ __align__(16) float g_m2[NN * 64];

namespace {
cudaStream_t g_side = nullptr;
cudaEvent_t  g_ev_fork = nullptr, g_ev_join = nullptr;
struct Init {
    Init() {
        if (cudaStreamCreateWithFlags(&g_side, cudaStreamNonBlocking) != cudaSuccess)
            g_side = nullptr;
        if (cudaEventCreateWithFlags(&g_ev_fork, cudaEventDisableTiming) != cudaSuccess)
            g_ev_fork = nullptr;
        if (cudaEventCreateWithFlags(&g_ev_join, cudaEventDisableTiming) != cudaSuccess)
            g_ev_join = nullptr;
    }
};
static Init s_init;
}

// ---------------------------------------------------------------------------
// CSR build
// ---------------------------------------------------------------------------
__global__ void zero_hist_kernel(int* __restrict__ hist) {
    int i = blockIdx.x * 256 + threadIdx.x;
    if (i < NN) hist[i] = 0;
}

__global__ void hist_kernel(const int* __restrict__ dst, int* __restrict__ hist) {
    int e = blockIdx.x * 256 + threadIdx.x;
    if (e < EE) atomicAdd(&hist[dst[e]], 1);
}

__global__ void scan1_kernel(const int* __restrict__ hist, int* __restrict__ row_ptr,
                             int* __restrict__ part)
{
    int gi = blockIdx.x * 1024 + threadIdx.x;
    int v = (gi < NN) ? hist[gi] : 0;
    int lane = threadIdx.x & 31, wid = threadIdx.x >> 5;

    int x = v;
#pragma unroll
    for (int o = 1; o < 32; o <<= 1) {
        int t = __shfl_up_sync(0xffffffffu, x, o);
        if (lane >= o) x += t;
    }
    __shared__ int wsum[32];
    if (lane == 31) wsum[wid] = x;
    __syncthreads();
    if (wid == 0) {
        int y = wsum[lane];
#pragma unroll
        for (int o = 1; o < 32; o <<= 1) {
            int t = __shfl_up_sync(0xffffffffu, y, o);
            if (lane >= o) y += t;
        }
        wsum[lane] = y;
    }
    __syncthreads();
    int incl = x + (wid ? wsum[wid - 1] : 0);
    if (gi < NN) row_ptr[gi] = incl - v;
    if (threadIdx.x == 1023) part[blockIdx.x] = incl;
}

__global__ void scan2_kernel(int* __restrict__ part, int* __restrict__ row_ptr)
{
    int lane = threadIdx.x & 31, wid = threadIdx.x >> 5;
    int v = (threadIdx.x < SCAN_BLOCKS) ? part[threadIdx.x] : 0;
    int x = v;
#pragma unroll
    for (int o = 1; o < 32; o <<= 1) {
        int t = __shfl_up_sync(0xffffffffu, x, o);
        if (lane >= o) x += t;
    }
    __shared__ int ws[4];
    if (lane == 31) ws[wid] = x;
    __syncthreads();
    int add = 0;
    for (int w = 0; w < wid; w++) add += ws[w];
    int incl = x + add;
    if (threadIdx.x < SCAN_BLOCKS) part[threadIdx.x] = incl - v;
    if (threadIdx.x == SCAN_BLOCKS - 1) row_ptr[NN] = incl;
}

__global__ void scan3_kernel(int* __restrict__ row_ptr, const int* __restrict__ part,
                             const int* __restrict__ hist, int* __restrict__ cursor,
                             float* __restrict__ dis)
{
    int i = blockIdx.x * 1024 + threadIdx.x;
    if (i < NN) {
        int rp = row_ptr[i] + part[blockIdx.x];
        row_ptr[i] = rp;
        cursor[i] = rp;
        dis[i] = rsqrtf((float)(hist[i] + 1));
    }
}

__global__ void place_kernel(const int* __restrict__ src, const int* __restrict__ dst,
                             int* __restrict__ cursor, int* __restrict__ eidx) {
    int e = blockIdx.x * 256 + threadIdx.x;
    if (e >= EE) return;
    int d = dst[e];
    int slot = atomicAdd(&cursor[d], 1);
    eidx[slot] = src[e];
}

// ---------------------------------------------------------------------------
// TF32 tensor-core GEMM, R11 layout + double-buffered smem (1 barrier/K-tile).
// m = A @ W. A [M,K] row-major, W [K,BN] row-major. Block 128xBNx16, 8 warps
// (4m x 2n), warp tile 32 x BN/2. K % 16 == 0.
// ---------------------------------------------------------------------------
__device__ __forceinline__ float f2tf32(float x) {
    uint32_t u;
    asm("cvt.rna.tf32.f32 %0, %1;" : "=r"(u) : "f"(x));
    return __uint_as_float(u);
}

template<int BN>
__global__ __launch_bounds__(256, 2)
void gemm_tf32_kernel(const float* __restrict__ A, const float* __restrict__ W,
                      float* __restrict__ m, int M, int K)
{
    constexpr int BM = 128, BK = 16;
    constexpr int NFRAG = BN / 16;
    constexpr int PAD = 8;
    constexpr int AF4 = BM * BK / 4;          // 512
    constexpr int BF4 = BK * BN / 4;          // 512 / 256
    constexpr int APT = AF4 / 256;            // 2
    constexpr int BPT = (BF4 + 255) / 256;    // 2 / 1

    __shared__ float As[2][BK][BM + PAD];
    __shared__ float Bs[2][BK][BN + PAD];

    const int tid = threadIdx.x;
    const int wid = tid >> 5, lane = tid & 31;
    const int gID = lane >> 2;
    const int tig = lane & 3;
    const int wm = (wid & 3) * 32;
    const int wn = (wid >> 2) * (BN / 2);
    const int row0 = blockIdx.x * BM;

    float c[2][NFRAG][4];
#pragma unroll
    for (int i = 0; i < 2; i++)
#pragma unroll
        for (int j = 0; j < NFRAG; j++)
#pragma unroll
            for (int q = 0; q < 4; q++) c[i][j][q] = 0.0f;

    float4 pa[APT], pb[BPT];

    auto loadA = [&](int kt) {
#pragma unroll
        for (int p = 0; p < APT; p++) {
            int i = tid + p * 256;
            int r  = i >> 2;
            int kc = (i & 3) * 4;
            int gr = row0 + r;
            pa[p] = (gr < M) ? *(const float4*)(A + (size_t)gr * K + kt + kc)
                             : make_float4(0.f, 0.f, 0.f, 0.f);
        }
    };
    auto loadB = [&](int kt) {
#pragma unroll
        for (int p = 0; p < BPT; p++) {
            int i = tid + p * 256;
            if (i < BF4) {
                int r  = i / (BN / 4);
                int cc = (i % (BN / 4)) * 4;
                pb[p] = *(const float4*)(W + (size_t)(kt + r) * BN + cc);
            }
        }
    };
    auto storeAB = [&](int buf) {
#pragma unroll
        for (int p = 0; p < APT; p++) {
            int i = tid + p * 256;
            int r  = i >> 2;
            int kc = (i & 3) * 4;
            As[buf][kc + 0][r] = f2tf32(pa[p].x);
            As[buf][kc + 1][r] = f2tf32(pa[p].y);
            As[buf][kc + 2][r] = f2tf32(pa[p].z);
            As[buf][kc + 3][r] = f2tf32(pa[p].w);
        }
#pragma unroll
        for (int p = 0; p < BPT; p++) {
            int i = tid + p * 256;
            if (i < BF4) {
                int r  = i / (BN / 4);
                int cc = (i % (BN / 4)) * 4;
                Bs[buf][r][cc + 0] = f2tf32(pb[p].x);
                Bs[buf][r][cc + 1] = f2tf32(pb[p].y);
                Bs[buf][r][cc + 2] = f2tf32(pb[p].z);
                Bs[buf][r][cc + 3] = f2tf32(pb[p].w);
            }
        }
    };

    auto compute = [&](int buf) {
#pragma unroll
        for (int ks = 0; ks < 2; ks++) {
            const int k0 = ks * 8;
            uint32_t af[2][4];
#pragma unroll
            for (int i = 0; i < 2; i++) {
                int mi = wm + i * 16;
                af[i][0] = __float_as_uint(As[buf][k0 + tig    ][mi + gID    ]);
                af[i][1] = __float_as_uint(As[buf][k0 + tig    ][mi + gID + 8]);
                af[i][2] = __float_as_uint(As[buf][k0 + tig + 4][mi + gID    ]);
                af[i][3] = __float_as_uint(As[buf][k0 + tig + 4][mi + gID + 8]);
            }
            uint32_t bf[NFRAG][2];
#pragma unroll
            for (int j = 0; j < NFRAG; j++) {
                int nj = wn + j * 8;
                bf[j][0] = __float_as_uint(Bs[buf][k0 + tig    ][nj + gID]);
                bf[j][1] = __float_as_uint(Bs[buf][k0 + tig + 4][nj + gID]);
            }
#pragma unroll
            for (int i = 0; i < 2; i++)
#pragma unroll
                for (int j = 0; j < NFRAG; j++) {
                    asm volatile(
                        "mma.sync.aligned.m16n8k8.row.col.f32.tf32.tf32.f32 "
                        "{%0,%1,%2,%3}, {%4,%5,%6,%7}, {%8,%9}, {%0,%1,%2,%3};"
                        : "+f"(c[i][j][0]), "+f"(c[i][j][1]),
                          "+f"(c[i][j][2]), "+f"(c[i][j][3])
                        : "r"(af[i][0]), "r"(af[i][1]), "r"(af[i][2]), "r"(af[i][3]),
                          "r"(bf[j][0]), "r"(bf[j][1]));
                }
        }
    };

    const int T = K / BK;
    loadA(0); loadB(0);
    storeAB(0);
    __syncthreads();

    for (int t = 0; t < T; t++) {
        if (t + 1 < T) { loadA((t + 1) * BK); loadB((t + 1) * BK); }
        compute(t & 1);
        if (t + 1 < T) {
            storeAB((t + 1) & 1);
            __syncthreads();
        }
    }

#pragma unroll
    for (int i = 0; i < 2; i++) {
#pragma unroll
        for (int j = 0; j < NFRAG; j++) {
            int gcol = wn + j * 8 + 2 * tig;
            int grow0 = row0 + wm + i * 16 + gID;
            if (grow0 < M)
                *(float2*)(m + (size_t)grow0 * BN + gcol) =
                    make_float2(c[i][j][0], c[i][j][1]);
            int grow1 = grow0 + 8;
            if (grow1 < M)
                *(float2*)(m + (size_t)grow1 * BN + gcol) =
                    make_float2(c[i][j][2], c[i][j][3]);
        }
    }
}

// ---------------------------------------------------------------------------
// Gather aggregation, warp per node, dis applied at gather time.
// ---------------------------------------------------------------------------
__global__ __launch_bounds__(256)
void gather1_kernel(const float* __restrict__ m1, float* __restrict__ h1,
                    const int* __restrict__ row_ptr, const int* __restrict__ eidx,
                    const float* __restrict__ dis, const float* __restrict__ b1)
{
    int n = blockIdx.x * 8 + (threadIdx.x >> 5);
    if (n >= NN) return;
    int lane = threadIdx.x & 31;

    int start = row_ptr[n];
    int end   = row_ptr[n + 1];
    float dn = dis[n];

    float4 mv = *(const float4*)(m1 + (size_t)n * 128 + lane * 4);
    float4 acc;
    acc.x = dn * mv.x; acc.y = dn * mv.y; acc.z = dn * mv.z; acc.w = dn * mv.w;

    int e = start;
    for (; e + 4 <= end; e += 4) {
        int s0 = __ldg(eidx + e);
        int s1 = __ldg(eidx + e + 1);
        int s2 = __ldg(eidx + e + 2);
        int s3 = __ldg(eidx + e + 3);
        float d0 = __ldg(dis + s0), d1 = __ldg(dis + s1);
        float d2 = __ldg(dis + s2), d3 = __ldg(dis + s3);
        float4 v0 = *(const float4*)(m1 + (size_t)s0 * 128 + lane * 4);
        float4 v1 = *(const float4*)(m1 + (size_t)s1 * 128 + lane * 4);
        float4 v2 = *(const float4*)(m1 + (size_t)s2 * 128 + lane * 4);
        float4 v3 = *(const float4*)(m1 + (size_t)s3 * 128 + lane * 4);
        acc.x = fmaf(d0, v0.x, fmaf(d1, v1.x, fmaf(d2, v2.x, fmaf(d3, v3.x, acc.x))));
        acc.y = fmaf(d0, v0.y, fmaf(d1, v1.y, fmaf(d2, v2.y, fmaf(d3, v3.y, acc.y))));
        acc.z = fmaf(d0, v0.z, fmaf(d1, v1.z, fmaf(d2, v2.z, fmaf(d3, v3.z, acc.z))));
        acc.w = fmaf(d0, v0.w, fmaf(d1, v1.w, fmaf(d2, v2.w, fmaf(d3, v3.w, acc.w))));
    }
    for (; e < end; e++) {
        int s0 = __ldg(eidx + e);
        float d0 = __ldg(dis + s0);
        float4 v0 = *(const float4*)(m1 + (size_t)s0 * 128 + lane * 4);
        acc.x = fmaf(d0, v0.x, acc.x);
        acc.y = fmaf(d0, v0.y, acc.y);
        acc.z = fmaf(d0, v0.z, acc.z);
        acc.w = fmaf(d0, v0.w, acc.w);
    }

    float4 b = *(const float4*)(b1 + lane * 4);
    float4 o;
    o.x = fmaxf(fmaf(acc.x, dn, b.x), 0.f);
    o.y = fmaxf(fmaf(acc.y, dn, b.y), 0.f);
    o.z = fmaxf(fmaf(acc.z, dn, b.z), 0.f);
    o.w = fmaxf(fmaf(acc.w, dn, b.w), 0.f);
    *(float4*)(h1 + (size_t)n * 128 + lane * 4) = o;
}

__global__ __launch_bounds__(256)
void gather2_kernel(const float* __restrict__ m2, float* __restrict__ out,
                    const int* __restrict__ row_ptr, const int* __restrict__ eidx,
                    const float* __restrict__ dis, const float* __restrict__ b2)
{
    int n = blockIdx.x * 8 + (threadIdx.x >> 5);
    if (n >= NN) return;
    int lane = threadIdx.x & 31;

    int start = row_ptr[n];
    int end   = row_ptr[n + 1];
    float dn = dis[n];

    float2 mv = *(const float2*)(m2 + (size_t)n * 64 + lane * 2);
    float2 acc;
    acc.x = dn * mv.x; acc.y = dn * mv.y;

    int e = start;
    for (; e + 4 <= end; e += 4) {
        int s0 = __ldg(eidx + e);
        int s1 = __ldg(eidx + e + 1);
        int s2 = __ldg(eidx + e + 2);
        int s3 = __ldg(eidx + e + 3);
        float d0 = __ldg(dis + s0), d1 = __ldg(dis + s1);
        float d2 = __ldg(dis + s2), d3 = __ldg(dis + s3);
        float2 v0 = *(const float2*)(m2 + (size_t)s0 * 64 + lane * 2);
        float2 v1 = *(const float2*)(m2 + (size_t)s1 * 64 + lane * 2);
        float2 v2 = *(const float2*)(m2 + (size_t)s2 * 64 + lane * 2);
        float2 v3 = *(const float2*)(m2 + (size_t)s3 * 64 + lane * 2);
        acc.x = fmaf(d0, v0.x, fmaf(d1, v1.x, fmaf(d2, v2.x, fmaf(d3, v3.x, acc.x))));
        acc.y = fmaf(d0, v0.y, fmaf(d1, v1.y, fmaf(d2, v2.y, fmaf(d3, v3.y, acc.y))));
    }
    for (; e < end; e++) {
        int s0 = __ldg(eidx + e);
        float d0 = __ldg(dis + s0);
        float2 v0 = *(const float2*)(m2 + (size_t)s0 * 64 + lane * 2);
        acc.x = fmaf(d0, v0.x, acc.x);
        acc.y = fmaf(d0, v0.y, acc.y);
    }

    float2 b = *(const float2*)(b2 + lane * 2);
    float2 o;
    o.x = fmaf(acc.x, dn, b.x);
    o.y = fmaf(acc.y, dn, b.y);
    *(float2*)(out + (size_t)n * 64 + lane * 2) = o;
}

// ---------------------------------------------------------------------------
extern "C" void kernel_launch(void* const* d_in, const int* in_sizes, int n_in,
                              void* d_out, int out_size)
{
    void *pv;
    cudaGetSymbolAddress(&pv, g_hist);    int*   hist    = (int*)pv;
    cudaGetSymbolAddress(&pv, g_row_ptr); int*   row_ptr = (int*)pv;
    cudaGetSymbolAddress(&pv, g_cursor);  int*   cursor  = (int*)pv;
    cudaGetSymbolAddress(&pv, g_part);    int*   part    = (int*)pv;
    cudaGetSymbolAddress(&pv, g_eidx);    int*   eidx    = (int*)pv;
    cudaGetSymbolAddress(&pv, g_dis);     float* dis     = (float*)pv;
    cudaGetSymbolAddress(&pv, g_m1);      float* m1      = (float*)pv;
    cudaGetSymbolAddress(&pv, g_h1);      float* h1      = (float*)pv;
    cudaGetSymbolAddress(&pv, g_m2);      float* m2      = (float*)pv;

    const long long elems[6] = {38400000LL, 49152LL, 128LL, 8192LL, 64LL, 6400000LL};
    const long long bytesz[6] = {38400000LL*4, 49152LL*4, 128LL*4, 8192LL*4, 64LL*4, 6400000LL*4};
    const void* ptr[6] = {nullptr,nullptr,nullptr,nullptr,nullptr,nullptr};

    int matched = 0;
    for (int i = 0; i < n_in && i < 16; i++)
        for (int j = 0; j < 6; j++)
            if ((long long)in_sizes[i] == elems[j] && !ptr[j]) { ptr[j] = d_in[i]; matched++; break; }
    if (matched < 6) {
        for (int j = 0; j < 6; j++) ptr[j] = nullptr;
        matched = 0;
        for (int i = 0; i < n_in && i < 16; i++)
            for (int j = 0; j < 6; j++)
                if ((long long)in_sizes[i] == bytesz[j] && !ptr[j]) { ptr[j] = d_in[i]; matched++; break; }
    }
    if (matched < 6 && n_in >= 6)
        for (int j = 0; j < 6; j++) ptr[j] = d_in[j];

    const float* x  = (const float*)ptr[0];
    const float* W1 = (const float*)ptr[1];
    const float* b1 = (const float*)ptr[2];
    const float* W2 = (const float*)ptr[3];
    const float* b2 = (const float*)ptr[4];
    const int*   ei = (const int*)  ptr[5];
    const int* src = ei;
    const int* dst = ei + EE;
    float* out = (float*)d_out;

    const bool fork = (g_side && g_ev_fork && g_ev_join);
    cudaStream_t s_csr = fork ? g_side : (cudaStream_t)0;

    if (fork) {
        cudaEventRecord(g_ev_fork, 0);
        cudaStreamWaitEvent(g_side, g_ev_fork, 0);
    }

    // CSR build on side stream; gemm1 is the 4th launch (profiler slot).
    zero_hist_kernel<<<(NN + 255) / 256, 256, 0, s_csr>>>(hist);
    hist_kernel     <<<(EE + 255) / 256, 256, 0, s_csr>>>(dst, hist);
    scan1_kernel    <<<SCAN_BLOCKS, 1024, 0, s_csr>>>(hist, row_ptr, part);

    gemm_tf32_kernel<128><<<(NN + 127) / 128, 256>>>(x, W1, m1, NN, 384);

    scan2_kernel    <<<1, 128, 0, s_csr>>>(part, row_ptr);
    scan3_kernel    <<<SCAN_BLOCKS, 1024, 0, s_csr>>>(row_ptr, part, hist, cursor, dis);
    place_kernel    <<<(EE + 255) / 256, 256, 0, s_csr>>>(src, dst, cursor, eidx);
    if (fork) cudaEventRecord(g_ev_join, g_side);

    if (fork) cudaStreamWaitEvent((cudaStream_t)0, g_ev_join, 0);

    gather1_kernel<<<(NN + 7) / 8, 256>>>(m1, h1, row_ptr, eidx, dis, b1);

    gemm_tf32_kernel<64><<<(NN + 127) / 128, 256>>>(h1, W2, m2, NN, 128);

    gather2_kernel<<<(NN + 7) / 8, 256>>>(m2, out, row_ptr, eidx, dis, b2);
}

// round 14
// speedup vs baseline: 1.5914x; 1.0526x over previous
#include <cuda_runtime.h>
#include <cstdint>

// 2-layer GCN, N=100000, E=3200000, 384 -> 128 -> 64.
// TF32 tensor-core GEMMs with cp.async 3-stage pipeline; gathers apply dis.
// W pre-rounded to tf32 (RNA); A fragments rounded at read (no truncation bias).
// All __device__ buffers via cudaGetSymbolAddress (GB300/ATS host-shadow trap).

#define NN 100000
#define EE 3200000
#define SCAN_BLOCKS 98   // ceil(100000/1024)

__device__ int   g_hist[NN];
__device__ int   g_row_ptr[NN + 1];
__device__ int   g_cursor[NN];
__device__ int   g_part[SCAN_BLOCKS];
__device__ int   g_eidx[EE];
__device__ float g_dis[NN];
__device__ __align__(16) float g_m1[NN * 128];
__device__ __align__(16) float g_h1[NN * 128];
__device__ __align__(16) float g_m2[NN * 64];
__device__ __align__(16) float g_w1r[384 * 128];
__device__ __align__(16) float g_w2r[128 * 64];

namespace {
cudaStream_t g_side = nullptr;
cudaEvent_t  g_ev_fork = nullptr, g_ev_join = nullptr;
struct Init {
    Init() {
        if (cudaStreamCreateWithFlags(&g_side, cudaStreamNonBlocking) != cudaSuccess)
            g_side = nullptr;
        if (cudaEventCreateWithFlags(&g_ev_fork, cudaEventDisableTiming) != cudaSuccess)
            g_ev_fork = nullptr;
        if (cudaEventCreateWithFlags(&g_ev_join, cudaEventDisableTiming) != cudaSuccess)
            g_ev_join = nullptr;
    }
};
static Init s_init;
}

__device__ __forceinline__ float f2tf32(float x) {
    uint32_t u;
    asm("cvt.rna.tf32.f32 %0, %1;" : "=r"(u) : "f"(x));
    return __uint_as_float(u);
}
__device__ __forceinline__ uint32_t f2tf32_bits(float x) {
    uint32_t u;
    asm("cvt.rna.tf32.f32 %0, %1;" : "=r"(u) : "f"(x));
    return u;
}

// ---------------------------------------------------------------------------
// CSR build
// ---------------------------------------------------------------------------
__global__ void zero_hist_kernel(int* __restrict__ hist) {
    int i = blockIdx.x * 256 + threadIdx.x;
    if (i < NN) hist[i] = 0;
}

__global__ void hist_kernel(const int* __restrict__ dst, int* __restrict__ hist) {
    int e = blockIdx.x * 256 + threadIdx.x;
    if (e < EE) atomicAdd(&hist[dst[e]], 1);
}

__global__ void scan1_kernel(const int* __restrict__ hist, int* __restrict__ row_ptr,
                             int* __restrict__ part)
{
    int gi = blockIdx.x * 1024 + threadIdx.x;
    int v = (gi < NN) ? hist[gi] : 0;
    int lane = threadIdx.x & 31, wid = threadIdx.x >> 5;

    int x = v;
#pragma unroll
    for (int o = 1; o < 32; o <<= 1) {
        int t = __shfl_up_sync(0xffffffffu, x, o);
        if (lane >= o) x += t;
    }
    __shared__ int wsum[32];
    if (lane == 31) wsum[wid] = x;
    __syncthreads();
    if (wid == 0) {
        int y = wsum[lane];
#pragma unroll
        for (int o = 1; o < 32; o <<= 1) {
            int t = __shfl_up_sync(0xffffffffu, y, o);
            if (lane >= o) y += t;
        }
        wsum[lane] = y;
    }
    __syncthreads();
    int incl = x + (wid ? wsum[wid - 1] : 0);
    if (gi < NN) row_ptr[gi] = incl - v;
    if (threadIdx.x == 1023) part[blockIdx.x] = incl;
}

__global__ void scan2_kernel(int* __restrict__ part, int* __restrict__ row_ptr)
{
    int lane = threadIdx.x & 31, wid = threadIdx.x >> 5;
    int v = (threadIdx.x < SCAN_BLOCKS) ? part[threadIdx.x] : 0;
    int x = v;
#pragma unroll
    for (int o = 1; o < 32; o <<= 1) {
        int t = __shfl_up_sync(0xffffffffu, x, o);
        if (lane >= o) x += t;
    }
    __shared__ int ws[4];
    if (lane == 31) ws[wid] = x;
    __syncthreads();
    int add = 0;
    for (int w = 0; w < wid; w++) add += ws[w];
    int incl = x + add;
    if (threadIdx.x < SCAN_BLOCKS) part[threadIdx.x] = incl - v;
    if (threadIdx.x == SCAN_BLOCKS - 1) row_ptr[NN] = incl;
}

__global__ void scan3_kernel(int* __restrict__ row_ptr, const int* __restrict__ part,
                             const int* __restrict__ hist, int* __restrict__ cursor,
                             float* __restrict__ dis)
{
    int i = blockIdx.x * 1024 + threadIdx.x;
    if (i < NN) {
        int rp = row_ptr[i] + part[blockIdx.x];
        row_ptr[i] = rp;
        cursor[i] = rp;
        dis[i] = rsqrtf((float)(hist[i] + 1));
    }
}

__global__ void place_kernel(const int* __restrict__ src, const int* __restrict__ dst,
                             int* __restrict__ cursor, int* __restrict__ eidx) {
    int e = blockIdx.x * 256 + threadIdx.x;
    if (e >= EE) return;
    int d = dst[e];
    int slot = atomicAdd(&cursor[d], 1);
    eidx[slot] = src[e];
}

// Pre-round weights to tf32 (RNA) so B needs no cvt in the GEMM.
__global__ void round_w_kernel(const float* __restrict__ w1, const float* __restrict__ w2,
                               float* __restrict__ w1r, float* __restrict__ w2r)
{
    int i = blockIdx.x * 256 + threadIdx.x;
    if (i < 384 * 128) w1r[i] = f2tf32(w1[i]);
    if (i < 128 * 64)  w2r[i] = f2tf32(w2[i]);
}

// ---------------------------------------------------------------------------
// TF32 tensor-core GEMM, cp.async 3-stage pipeline.
// m = A @ W. A [M,K] row-major fp32 (rounded at read), W [K,BN] pre-rounded.
// Block 128 x BN x 16, 8 warps (4m x 2n), warp tile 32 x BN/2. K % 16 == 0.
// Smem: A as [m][k] stride 20 (conflict-free frag reads), B [k][n] stride BN+8.
// ---------------------------------------------------------------------------
template<int BN>
__global__ __launch_bounds__(256)
void gemm_tf32_async(const float* __restrict__ A, const float* __restrict__ W,
                     float* __restrict__ m, int M, int K)
{
    constexpr int BM = 128, BK = 16, S = 3;
    constexpr int NFRAG = BN / 16;
    constexpr int ASTR = 20;                 // floats per A smem row
    constexpr int BSTR = BN + 8;             // 136 / 72
    constexpr int ASZ = BM * ASTR;           // floats per A stage
    constexpr int BSZ = BK * BSTR;           // floats per B stage
    constexpr int BCH = BK * BN / 4;         // B 16B chunks per tile
    constexpr int BPT = (BCH + 255) / 256;

    extern __shared__ float smem[];
    float* As = smem;                        // [S][ASZ]
    float* Bs = smem + S * ASZ;              // [S][BSZ]

    const int tid = threadIdx.x;
    const int wid = tid >> 5, lane = tid & 31;
    const int gID = lane >> 2;
    const int tig = lane & 3;
    const int wm = (wid & 3) * 32;
    const int wn = (wid >> 2) * (BN / 2);
    const int row0 = blockIdx.x * BM;

    float c[2][NFRAG][4];
#pragma unroll
    for (int i = 0; i < 2; i++)
#pragma unroll
        for (int j = 0; j < NFRAG; j++)
#pragma unroll
            for (int q = 0; q < 4; q++) c[i][j][q] = 0.0f;

    auto issue_tile = [&](int kt, int stg) {
        // A: 128 rows x 16 floats = 512 chunks of 16B, 2 per thread
#pragma unroll
        for (int p = 0; p < 2; p++) {
            int i = tid + p * 256;
            int r = i >> 2;
            int cc = (i & 3) * 4;
            int gr = row0 + r;
            int sz = (gr < M) ? 16 : 0;
            if (gr >= M) gr = M - 1;                    // keep address in-bounds
            const float* g = A + (size_t)gr * K + kt + cc;
            uint32_t s = (uint32_t)__cvta_generic_to_shared(
                &As[stg * ASZ + r * ASTR + cc]);
            asm volatile("cp.async.cg.shared.global [%0], [%1], 16, %2;"
                         :: "r"(s), "l"(g), "r"(sz));
        }
        // B: BK x BN = BCH chunks
#pragma unroll
        for (int p = 0; p < BPT; p++) {
            int i = tid + p * 256;
            if (i < BCH) {
                int r  = i / (BN / 4);
                int cc = (i % (BN / 4)) * 4;
                const float* g = W + (size_t)(kt + r) * BN + cc;
                uint32_t s = (uint32_t)__cvta_generic_to_shared(
                    &Bs[stg * BSZ + r * BSTR + cc]);
                asm volatile("cp.async.cg.shared.global [%0], [%1], 16, %2;"
                             :: "r"(s), "l"(g), "r"(16));
            }
        }
    };

    auto compute = [&](int buf) {
        const float* a = As + buf * ASZ;
        const float* b = Bs + buf * BSZ;
#pragma unroll
        for (int ks = 0; ks < 2; ks++) {
            const int k0 = ks * 8;
            uint32_t af[2][4];
#pragma unroll
            for (int i = 0; i < 2; i++) {
                int mi = wm + i * 16 + gID;
                af[i][0] = f2tf32_bits(a[(mi    ) * ASTR + k0 + tig    ]);
                af[i][1] = f2tf32_bits(a[(mi + 8) * ASTR + k0 + tig    ]);
                af[i][2] = f2tf32_bits(a[(mi    ) * ASTR + k0 + tig + 4]);
                af[i][3] = f2tf32_bits(a[(mi + 8) * ASTR + k0 + tig + 4]);
            }
            uint32_t bf[NFRAG][2];
#pragma unroll
            for (int j = 0; j < NFRAG; j++) {
                int nj = wn + j * 8 + gID;
                bf[j][0] = __float_as_uint(b[(k0 + tig    ) * BSTR + nj]);
                bf[j][1] = __float_as_uint(b[(k0 + tig + 4) * BSTR + nj]);
            }
#pragma unroll
            for (int i = 0; i < 2; i++)
#pragma unroll
                for (int j = 0; j < NFRAG; j++) {
                    asm volatile(
                        "mma.sync.aligned.m16n8k8.row.col.f32.tf32.tf32.f32 "
                        "{%0,%1,%2,%3}, {%4,%5,%6,%7}, {%8,%9}, {%0,%1,%2,%3};"
                        : "+f"(c[i][j][0]), "+f"(c[i][j][1]),
                          "+f"(c[i][j][2]), "+f"(c[i][j][3])
                        : "r"(af[i][0]), "r"(af[i][1]), "r"(af[i][2]), "r"(af[i][3]),
                          "r"(bf[j][0]), "r"(bf[j][1]));
                }
        }
    };

    const int T = K / BK;
    // prologue: tiles 0..S-2, one commit group each
#pragma unroll
    for (int s = 0; s < S - 1; s++) {
        if (s < T) issue_tile(s * BK, s);
        asm volatile("cp.async.commit_group;" ::: "memory");
    }

    for (int t = 0; t < T; t++) {
        asm volatile("cp.async.wait_group 1;" ::: "memory");   // S-2 == 1
        __syncthreads();
        int tn = t + S - 1;
        if (tn < T) issue_tile(tn * BK, tn % S);
        asm volatile("cp.async.commit_group;" ::: "memory");
        compute(t % S);
    }

#pragma unroll
    for (int i = 0; i < 2; i++) {
#pragma unroll
        for (int j = 0; j < NFRAG; j++) {
            int gcol = wn + j * 8 + 2 * tig;
            int grow0 = row0 + wm + i * 16 + gID;
            if (grow0 < M)
                *(float2*)(m + (size_t)grow0 * BN + gcol) =
                    make_float2(c[i][j][0], c[i][j][1]);
            int grow1 = grow0 + 8;
            if (grow1 < M)
                *(float2*)(m + (size_t)grow1 * BN + gcol) =
                    make_float2(c[i][j][2], c[i][j][3]);
        }
    }
}

// ---------------------------------------------------------------------------
// Gather aggregation, warp per node, dis applied at gather time.
// ---------------------------------------------------------------------------
__global__ __launch_bounds__(256)
void gather1_kernel(const float* __restrict__ m1, float* __restrict__ h1,
                    const int* __restrict__ row_ptr, const int* __restrict__ eidx,
                    const float* __restrict__ dis, const float* __restrict__ b1)
{
    int n = blockIdx.x * 8 + (threadIdx.x >> 5);
    if (n >= NN) return;
    int lane = threadIdx.x & 31;

    int start = row_ptr[n];
    int end   = row_ptr[n + 1];
    float dn = dis[n];

    float4 mv = *(const float4*)(m1 + (size_t)n * 128 + lane * 4);
    float4 acc;
    acc.x = dn * mv.x; acc.y = dn * mv.y; acc.z = dn * mv.z; acc.w = dn * mv.w;

    int e = start;
    for (; e + 4 <= end; e += 4) {
        int s0 = __ldg(eidx + e);
        int s1 = __ldg(eidx + e + 1);
        int s2 = __ldg(eidx + e + 2);
        int s3 = __ldg(eidx + e + 3);
        float d0 = __ldg(dis + s0), d1 = __ldg(dis + s1);
        float d2 = __ldg(dis + s2), d3 = __ldg(dis + s3);
        float4 v0 = *(const float4*)(m1 + (size_t)s0 * 128 + lane * 4);
        float4 v1 = *(const float4*)(m1 + (size_t)s1 * 128 + lane * 4);
        float4 v2 = *(const float4*)(m1 + (size_t)s2 * 128 + lane * 4);
        float4 v3 = *(const float4*)(m1 + (size_t)s3 * 128 + lane * 4);
        acc.x = fmaf(d0, v0.x, fmaf(d1, v1.x, fmaf(d2, v2.x, fmaf(d3, v3.x, acc.x))));
        acc.y = fmaf(d0, v0.y, fmaf(d1, v1.y, fmaf(d2, v2.y, fmaf(d3, v3.y, acc.y))));
        acc.z = fmaf(d0, v0.z, fmaf(d1, v1.z, fmaf(d2, v2.z, fmaf(d3, v3.z, acc.z))));
        acc.w = fmaf(d0, v0.w, fmaf(d1, v1.w, fmaf(d2, v2.w, fmaf(d3, v3.w, acc.w))));
    }
    for (; e < end; e++) {
        int s0 = __ldg(eidx + e);
        float d0 = __ldg(dis + s0);
        float4 v0 = *(const float4*)(m1 + (size_t)s0 * 128 + lane * 4);
        acc.x = fmaf(d0, v0.x, acc.x);
        acc.y = fmaf(d0, v0.y, acc.y);
        acc.z = fmaf(d0, v0.z, acc.z);
        acc.w = fmaf(d0, v0.w, acc.w);
    }

    float4 b = *(const float4*)(b1 + lane * 4);
    float4 o;
    o.x = fmaxf(fmaf(acc.x, dn, b.x), 0.f);
    o.y = fmaxf(fmaf(acc.y, dn, b.y), 0.f);
    o.z = fmaxf(fmaf(acc.z, dn, b.z), 0.f);
    o.w = fmaxf(fmaf(acc.w, dn, b.w), 0.f);
    *(float4*)(h1 + (size_t)n * 128 + lane * 4) = o;
}

__global__ __launch_bounds__(256)
void gather2_kernel(const float* __restrict__ m2, float* __restrict__ out,
                    const int* __restrict__ row_ptr, const int* __restrict__ eidx,
                    const float* __restrict__ dis, const float* __restrict__ b2)
{
    int n = blockIdx.x * 8 + (threadIdx.x >> 5);
    if (n >= NN) return;
    int lane = threadIdx.x & 31;

    int start = row_ptr[n];
    int end   = row_ptr[n + 1];
    float dn = dis[n];

    float2 mv = *(const float2*)(m2 + (size_t)n * 64 + lane * 2);
    float2 acc;
    acc.x = dn * mv.x; acc.y = dn * mv.y;

    int e = start;
    for (; e + 4 <= end; e += 4) {
        int s0 = __ldg(eidx + e);
        int s1 = __ldg(eidx + e + 1);
        int s2 = __ldg(eidx + e + 2);
        int s3 = __ldg(eidx + e + 3);
        float d0 = __ldg(dis + s0), d1 = __ldg(dis + s1);
        float d2 = __ldg(dis + s2), d3 = __ldg(dis + s3);
        float2 v0 = *(const float2*)(m2 + (size_t)s0 * 64 + lane * 2);
        float2 v1 = *(const float2*)(m2 + (size_t)s1 * 64 + lane * 2);
        float2 v2 = *(const float2*)(m2 + (size_t)s2 * 64 + lane * 2);
        float2 v3 = *(const float2*)(m2 + (size_t)s3 * 64 + lane * 2);
        acc.x = fmaf(d0, v0.x, fmaf(d1, v1.x, fmaf(d2, v2.x, fmaf(d3, v3.x, acc.x))));
        acc.y = fmaf(d0, v0.y, fmaf(d1, v1.y, fmaf(d2, v2.y, fmaf(d3, v3.y, acc.y))));
    }
    for (; e < end; e++) {
        int s0 = __ldg(eidx + e);
        float d0 = __ldg(dis + s0);
        float2 v0 = *(const float2*)(m2 + (size_t)s0 * 64 + lane * 2);
        acc.x = fmaf(d0, v0.x, acc.x);
        acc.y = fmaf(d0, v0.y, acc.y);
    }

    float2 b = *(const float2*)(b2 + lane * 2);
    float2 o;
    o.x = fmaf(acc.x, dn, b.x);
    o.y = fmaf(acc.y, dn, b.y);
    *(float2*)(out + (size_t)n * 64 + lane * 2) = o;
}

// ---------------------------------------------------------------------------
extern "C" void kernel_launch(void* const* d_in, const int* in_sizes, int n_in,
                              void* d_out, int out_size)
{
    void *pv;
    cudaGetSymbolAddress(&pv, g_hist);    int*   hist    = (int*)pv;
    cudaGetSymbolAddress(&pv, g_row_ptr); int*   row_ptr = (int*)pv;
    cudaGetSymbolAddress(&pv, g_cursor);  int*   cursor  = (int*)pv;
    cudaGetSymbolAddress(&pv, g_part);    int*   part    = (int*)pv;
    cudaGetSymbolAddress(&pv, g_eidx);    int*   eidx    = (int*)pv;
    cudaGetSymbolAddress(&pv, g_dis);     float* dis     = (float*)pv;
    cudaGetSymbolAddress(&pv, g_m1);      float* m1      = (float*)pv;
    cudaGetSymbolAddress(&pv, g_h1);      float* h1      = (float*)pv;
    cudaGetSymbolAddress(&pv, g_m2);      float* m2      = (float*)pv;
    cudaGetSymbolAddress(&pv, g_w1r);     float* w1r     = (float*)pv;
    cudaGetSymbolAddress(&pv, g_w2r);     float* w2r     = (float*)pv;

    const long long elems[6] = {38400000LL, 49152LL, 128LL, 8192LL, 64LL, 6400000LL};
    const long long bytesz[6] = {38400000LL*4, 49152LL*4, 128LL*4, 8192LL*4, 64LL*4, 6400000LL*4};
    const void* ptr[6] = {nullptr,nullptr,nullptr,nullptr,nullptr,nullptr};

    int matched = 0;
    for (int i = 0; i < n_in && i < 16; i++)
        for (int j = 0; j < 6; j++)
            if ((long long)in_sizes[i] == elems[j] && !ptr[j]) { ptr[j] = d_in[i]; matched++; break; }
    if (matched < 6) {
        for (int j = 0; j < 6; j++) ptr[j] = nullptr;
        matched = 0;
        for (int i = 0; i < n_in && i < 16; i++)
            for (int j = 0; j < 6; j++)
                if ((long long)in_sizes[i] == bytesz[j] && !ptr[j]) { ptr[j] = d_in[i]; matched++; break; }
    }
    if (matched < 6 && n_in >= 6)
        for (int j = 0; j < 6; j++) ptr[j] = d_in[j];

    const float* x  = (const float*)ptr[0];
    const float* W1 = (const float*)ptr[1];
    const float* b1 = (const float*)ptr[2];
    const float* W2 = (const float*)ptr[3];
    const float* b2 = (const float*)ptr[4];
    const int*   ei = (const int*)  ptr[5];
    const int* src = ei;
    const int* dst = ei + EE;
    float* out = (float*)d_out;

    // dynamic smem for the async GEMMs (3 stages): 128*20 + 16*(BN+8) floats/stage
    const int smem1 = 3 * (128 * 20 + 16 * 136) * 4;   // 56832 B  (BN=128)
    const int smem2 = 3 * (128 * 20 + 16 * 72) * 4;    // 44544 B  (BN=64)
    cudaFuncSetAttribute(gemm_tf32_async<128>,
                         cudaFuncAttributeMaxDynamicSharedMemorySize, smem1);
    cudaFuncSetAttribute(gemm_tf32_async<64>,
                         cudaFuncAttributeMaxDynamicSharedMemorySize, smem2);

    const bool fork = (g_side && g_ev_fork && g_ev_join);
    cudaStream_t s_csr = fork ? g_side : (cudaStream_t)0;

    if (fork) {
        cudaEventRecord(g_ev_fork, 0);
        cudaStreamWaitEvent(g_side, g_ev_fork, 0);
    }

    // launches 1-2: CSR start (side). launch 3: round_w (main). launch 4: gemm1.
    zero_hist_kernel<<<(NN + 255) / 256, 256, 0, s_csr>>>(hist);
    hist_kernel     <<<(EE + 255) / 256, 256, 0, s_csr>>>(dst, hist);

    round_w_kernel<<<(384 * 128 + 255) / 256, 256>>>(W1, W2, w1r, w2r);
    gemm_tf32_async<128><<<(NN + 127) / 128, 256, smem1>>>(x, w1r, m1, NN, 384);

    scan1_kernel    <<<SCAN_BLOCKS, 1024, 0, s_csr>>>(hist, row_ptr, part);
    scan2_kernel    <<<1, 128, 0, s_csr>>>(part, row_ptr);
    scan3_kernel    <<<SCAN_BLOCKS, 1024, 0, s_csr>>>(row_ptr, part, hist, cursor, dis);
    place_kernel    <<<(EE + 255) / 256, 256, 0, s_csr>>>(src, dst, cursor, eidx);
    if (fork) cudaEventRecord(g_ev_join, g_side);

    if (fork) cudaStreamWaitEvent((cudaStream_t)0, g_ev_join, 0);

    gather1_kernel<<<(NN + 7) / 8, 256>>>(m1, h1, row_ptr, eidx, dis, b1);

    gemm_tf32_async<64><<<(NN + 127) / 128, 256, smem2>>>(h1, w2r, m2, NN, 128);

    gather2_kernel<<<(NN + 7) / 8, 256>>>(m2, out, row_ptr, eidx, dis, b2);
}

// round 15
// speedup vs baseline: 1.6835x; 1.0578x over previous
#include <cuda_runtime.h>
#include <cuda_fp16.h>
#include <cstdint>

// 2-layer GCN, N=100000, E=3200000, 384 -> 128 -> 64.
// TF32 tensor-core GEMMs (cp.async pipeline) emit fp16 messages m1/m2;
// gathers read half-precision rows (halves L2 traffic — the R14 bottleneck),
// accumulate in fp32, apply dis at gather time. h1 stays fp32 for gemm2.
// All __device__ buffers via cudaGetSymbolAddress (GB300/ATS host-shadow trap).

#define NN 100000
#define EE 3200000
#define SCAN_BLOCKS 98   // ceil(100000/1024)

__device__ int   g_hist[NN];
__device__ int   g_row_ptr[NN + 1];
__device__ int   g_cursor[NN];
__device__ int   g_part[SCAN_BLOCKS];
__device__ int   g_eidx[EE];
__device__ float g_dis[NN];
__device__ __align__(16) __half g_m1h[NN * 128];
__device__ __align__(16) float  g_h1[NN * 128];
__device__ __align__(16) __half g_m2h[NN * 64];
__device__ __align__(16) float  g_w1r[384 * 128];
__device__ __align__(16) float  g_w2r[128 * 64];

namespace {
cudaStream_t g_side = nullptr;
cudaEvent_t  g_ev_fork = nullptr, g_ev_join = nullptr;
struct Init {
    Init() {
        if (cudaStreamCreateWithFlags(&g_side, cudaStreamNonBlocking) != cudaSuccess)
            g_side = nullptr;
        if (cudaEventCreateWithFlags(&g_ev_fork, cudaEventDisableTiming) != cudaSuccess)
            g_ev_fork = nullptr;
        if (cudaEventCreateWithFlags(&g_ev_join, cudaEventDisableTiming) != cudaSuccess)
            g_ev_join = nullptr;
    }
};
static Init s_init;
}

__device__ __forceinline__ float f2tf32(float x) {
    uint32_t u;
    asm("cvt.rna.tf32.f32 %0, %1;" : "=r"(u) : "f"(x));
    return __uint_as_float(u);
}
__device__ __forceinline__ uint32_t f2tf32_bits(float x) {
    uint32_t u;
    asm("cvt.rna.tf32.f32 %0, %1;" : "=r"(u) : "f"(x));
    return u;
}
__device__ __forceinline__ float4 h4_to_f4(uint2 r) {
    __half2 a = *(__half2*)&r.x;
    __half2 b = *(__half2*)&r.y;
    float2 fa = __half22float2(a);
    float2 fb = __half22float2(b);
    return make_float4(fa.x, fa.y, fb.x, fb.y);
}

// ---------------------------------------------------------------------------
// CSR build
// ---------------------------------------------------------------------------
__global__ void zero_hist_kernel(int* __restrict__ hist) {
    int i = blockIdx.x * 256 + threadIdx.x;
    if (i < NN) hist[i] = 0;
}

__global__ void hist_kernel(const int* __restrict__ dst, int* __restrict__ hist) {
    int e = blockIdx.x * 256 + threadIdx.x;
    if (e < EE) atomicAdd(&hist[dst[e]], 1);
}

__global__ void scan1_kernel(const int* __restrict__ hist, int* __restrict__ row_ptr,
                             int* __restrict__ part)
{
    int gi = blockIdx.x * 1024 + threadIdx.x;
    int v = (gi < NN) ? hist[gi] : 0;
    int lane = threadIdx.x & 31, wid = threadIdx.x >> 5;

    int x = v;
#pragma unroll
    for (int o = 1; o < 32; o <<= 1) {
        int t = __shfl_up_sync(0xffffffffu, x, o);
        if (lane >= o) x += t;
    }
    __shared__ int wsum[32];
    if (lane == 31) wsum[wid] = x;
    __syncthreads();
    if (wid == 0) {
        int y = wsum[lane];
#pragma unroll
        for (int o = 1; o < 32; o <<= 1) {
            int t = __shfl_up_sync(0xffffffffu, y, o);
            if (lane >= o) y += t;
        }
        wsum[lane] = y;
    }
    __syncthreads();
    int incl = x + (wid ? wsum[wid - 1] : 0);
    if (gi < NN) row_ptr[gi] = incl - v;
    if (threadIdx.x == 1023) part[blockIdx.x] = incl;
}

__global__ void scan2_kernel(int* __restrict__ part, int* __restrict__ row_ptr)
{
    int lane = threadIdx.x & 31, wid = threadIdx.x >> 5;
    int v = (threadIdx.x < SCAN_BLOCKS) ? part[threadIdx.x] : 0;
    int x = v;
#pragma unroll
    for (int o = 1; o < 32; o <<= 1) {
        int t = __shfl_up_sync(0xffffffffu, x, o);
        if (lane >= o) x += t;
    }
    __shared__ int ws[4];
    if (lane == 31) ws[wid] = x;
    __syncthreads();
    int add = 0;
    for (int w = 0; w < wid; w++) add += ws[w];
    int incl = x + add;
    if (threadIdx.x < SCAN_BLOCKS) part[threadIdx.x] = incl - v;
    if (threadIdx.x == SCAN_BLOCKS - 1) row_ptr[NN] = incl;
}

__global__ void scan3_kernel(int* __restrict__ row_ptr, const int* __restrict__ part,
                             const int* __restrict__ hist, int* __restrict__ cursor,
                             float* __restrict__ dis)
{
    int i = blockIdx.x * 1024 + threadIdx.x;
    if (i < NN) {
        int rp = row_ptr[i] + part[blockIdx.x];
        row_ptr[i] = rp;
        cursor[i] = rp;
        dis[i] = rsqrtf((float)(hist[i] + 1));
    }
}

__global__ void place_kernel(const int* __restrict__ src, const int* __restrict__ dst,
                             int* __restrict__ cursor, int* __restrict__ eidx) {
    int e = blockIdx.x * 256 + threadIdx.x;
    if (e >= EE) return;
    int d = dst[e];
    int slot = atomicAdd(&cursor[d], 1);
    eidx[slot] = src[e];
}

// Pre-round weights to tf32 (RNA).
__global__ void round_w_kernel(const float* __restrict__ w1, const float* __restrict__ w2,
                               float* __restrict__ w1r, float* __restrict__ w2r)
{
    int i = blockIdx.x * 256 + threadIdx.x;
    if (i < 384 * 128) w1r[i] = f2tf32(w1[i]);
    if (i < 128 * 64)  w2r[i] = f2tf32(w2[i]);
}

// ---------------------------------------------------------------------------
// TF32 tensor-core GEMM, cp.async 3-stage pipeline, fp16 output.
// m = A @ W. A [M,K] fp32 (tf32-rounded at frag read), W pre-rounded tf32.
// Block 128 x BN x 16, 8 warps (4m x 2n). K % 16 == 0.
// ---------------------------------------------------------------------------
template<int BN>
__global__ __launch_bounds__(256)
void gemm_tf32_async(const float* __restrict__ A, const float* __restrict__ W,
                     __half* __restrict__ m, int M, int K)
{
    constexpr int BM = 128, BK = 16, S = 3;
    constexpr int NFRAG = BN / 16;
    constexpr int ASTR = 20;
    constexpr int BSTR = BN + 8;
    constexpr int ASZ = BM * ASTR;
    constexpr int BSZ = BK * BSTR;
    constexpr int BCH = BK * BN / 4;
    constexpr int BPT = (BCH + 255) / 256;

    extern __shared__ float smem[];
    float* As = smem;
    float* Bs = smem + S * ASZ;

    const int tid = threadIdx.x;
    const int wid = tid >> 5, lane = tid & 31;
    const int gID = lane >> 2;
    const int tig = lane & 3;
    const int wm = (wid & 3) * 32;
    const int wn = (wid >> 2) * (BN / 2);
    const int row0 = blockIdx.x * BM;

    float c[2][NFRAG][4];
#pragma unroll
    for (int i = 0; i < 2; i++)
#pragma unroll
        for (int j = 0; j < NFRAG; j++)
#pragma unroll
            for (int q = 0; q < 4; q++) c[i][j][q] = 0.0f;

    auto issue_tile = [&](int kt, int stg) {
#pragma unroll
        for (int p = 0; p < 2; p++) {
            int i = tid + p * 256;
            int r = i >> 2;
            int cc = (i & 3) * 4;
            int gr = row0 + r;
            int sz = (gr < M) ? 16 : 0;
            if (gr >= M) gr = M - 1;
            const float* g = A + (size_t)gr * K + kt + cc;
            uint32_t s = (uint32_t)__cvta_generic_to_shared(
                &As[stg * ASZ + r * ASTR + cc]);
            asm volatile("cp.async.cg.shared.global [%0], [%1], 16, %2;"
                         :: "r"(s), "l"(g), "r"(sz));
        }
#pragma unroll
        for (int p = 0; p < BPT; p++) {
            int i = tid + p * 256;
            if (i < BCH) {
                int r  = i / (BN / 4);
                int cc = (i % (BN / 4)) * 4;
                const float* g = W + (size_t)(kt + r) * BN + cc;
                uint32_t s = (uint32_t)__cvta_generic_to_shared(
                    &Bs[stg * BSZ + r * BSTR + cc]);
                asm volatile("cp.async.cg.shared.global [%0], [%1], 16, %2;"
                             :: "r"(s), "l"(g), "r"(16));
            }
        }
    };

    auto compute = [&](int buf) {
        const float* a = As + buf * ASZ;
        const float* b = Bs + buf * BSZ;
#pragma unroll
        for (int ks = 0; ks < 2; ks++) {
            const int k0 = ks * 8;
            uint32_t af[2][4];
#pragma unroll
            for (int i = 0; i < 2; i++) {
                int mi = wm + i * 16 + gID;
                af[i][0] = f2tf32_bits(a[(mi    ) * ASTR + k0 + tig    ]);
                af[i][1] = f2tf32_bits(a[(mi + 8) * ASTR + k0 + tig    ]);
                af[i][2] = f2tf32_bits(a[(mi    ) * ASTR + k0 + tig + 4]);
                af[i][3] = f2tf32_bits(a[(mi + 8) * ASTR + k0 + tig + 4]);
            }
            uint32_t bf[NFRAG][2];
#pragma unroll
            for (int j = 0; j < NFRAG; j++) {
                int nj = wn + j * 8 + gID;
                bf[j][0] = __float_as_uint(b[(k0 + tig    ) * BSTR + nj]);
                bf[j][1] = __float_as_uint(b[(k0 + tig + 4) * BSTR + nj]);
            }
#pragma unroll
            for (int i = 0; i < 2; i++)
#pragma unroll
                for (int j = 0; j < NFRAG; j++) {
                    asm volatile(
                        "mma.sync.aligned.m16n8k8.row.col.f32.tf32.tf32.f32 "
                        "{%0,%1,%2,%3}, {%4,%5,%6,%7}, {%8,%9}, {%0,%1,%2,%3};"
                        : "+f"(c[i][j][0]), "+f"(c[i][j][1]),
                          "+f"(c[i][j][2]), "+f"(c[i][j][3])
                        : "r"(af[i][0]), "r"(af[i][1]), "r"(af[i][2]), "r"(af[i][3]),
                          "r"(bf[j][0]), "r"(bf[j][1]));
                }
        }
    };

    const int T = K / BK;
#pragma unroll
    for (int s = 0; s < S - 1; s++) {
        if (s < T) issue_tile(s * BK, s);
        asm volatile("cp.async.commit_group;" ::: "memory");
    }

    for (int t = 0; t < T; t++) {
        asm volatile("cp.async.wait_group 1;" ::: "memory");
        __syncthreads();
        int tn = t + S - 1;
        if (tn < T) issue_tile(tn * BK, tn % S);
        asm volatile("cp.async.commit_group;" ::: "memory");
        compute(t % S);
    }

    // epilogue: fp16 stores (half2 per fragment column pair; gcol even -> aligned)
#pragma unroll
    for (int i = 0; i < 2; i++) {
#pragma unroll
        for (int j = 0; j < NFRAG; j++) {
            int gcol = wn + j * 8 + 2 * tig;
            int grow0 = row0 + wm + i * 16 + gID;
            if (grow0 < M)
                *(__half2*)(m + (size_t)grow0 * BN + gcol) =
                    __floats2half2_rn(c[i][j][0], c[i][j][1]);
            int grow1 = grow0 + 8;
            if (grow1 < M)
                *(__half2*)(m + (size_t)grow1 * BN + gcol) =
                    __floats2half2_rn(c[i][j][2], c[i][j][3]);
        }
    }
}

// ---------------------------------------------------------------------------
// Gather aggregation, warp per node, fp16 message rows, fp32 accumulate.
// ---------------------------------------------------------------------------
__global__ __launch_bounds__(256)
void gather1_kernel(const __half* __restrict__ m1, float* __restrict__ h1,
                    const int* __restrict__ row_ptr, const int* __restrict__ eidx,
                    const float* __restrict__ dis, const float* __restrict__ b1)
{
    int n = blockIdx.x * 8 + (threadIdx.x >> 5);
    if (n >= NN) return;
    int lane = threadIdx.x & 31;           // handles halves [lane*4, lane*4+4)

    int start = row_ptr[n];
    int end   = row_ptr[n + 1];
    float dn = dis[n];

    float4 mv = h4_to_f4(*(const uint2*)(m1 + (size_t)n * 128 + lane * 4));
    float4 acc;
    acc.x = dn * mv.x; acc.y = dn * mv.y; acc.z = dn * mv.z; acc.w = dn * mv.w;

    int e = start;
    for (; e + 4 <= end; e += 4) {
        int s0 = __ldg(eidx + e);
        int s1 = __ldg(eidx + e + 1);
        int s2 = __ldg(eidx + e + 2);
        int s3 = __ldg(eidx + e + 3);
        float d0 = __ldg(dis + s0), d1 = __ldg(dis + s1);
        float d2 = __ldg(dis + s2), d3 = __ldg(dis + s3);
        float4 v0 = h4_to_f4(*(const uint2*)(m1 + (size_t)s0 * 128 + lane * 4));
        float4 v1 = h4_to_f4(*(const uint2*)(m1 + (size_t)s1 * 128 + lane * 4));
        float4 v2 = h4_to_f4(*(const uint2*)(m1 + (size_t)s2 * 128 + lane * 4));
        float4 v3 = h4_to_f4(*(const uint2*)(m1 + (size_t)s3 * 128 + lane * 4));
        acc.x = fmaf(d0, v0.x, fmaf(d1, v1.x, fmaf(d2, v2.x, fmaf(d3, v3.x, acc.x))));
        acc.y = fmaf(d0, v0.y, fmaf(d1, v1.y, fmaf(d2, v2.y, fmaf(d3, v3.y, acc.y))));
        acc.z = fmaf(d0, v0.z, fmaf(d1, v1.z, fmaf(d2, v2.z, fmaf(d3, v3.z, acc.z))));
        acc.w = fmaf(d0, v0.w, fmaf(d1, v1.w, fmaf(d2, v2.w, fmaf(d3, v3.w, acc.w))));
    }
    for (; e < end; e++) {
        int s0 = __ldg(eidx + e);
        float d0 = __ldg(dis + s0);
        float4 v0 = h4_to_f4(*(const uint2*)(m1 + (size_t)s0 * 128 + lane * 4));
        acc.x = fmaf(d0, v0.x, acc.x);
        acc.y = fmaf(d0, v0.y, acc.y);
        acc.z = fmaf(d0, v0.z, acc.z);
        acc.w = fmaf(d0, v0.w, acc.w);
    }

    float4 b = *(const float4*)(b1 + lane * 4);
    float4 o;
    o.x = fmaxf(fmaf(acc.x, dn, b.x), 0.f);
    o.y = fmaxf(fmaf(acc.y, dn, b.y), 0.f);
    o.z = fmaxf(fmaf(acc.z, dn, b.z), 0.f);
    o.w = fmaxf(fmaf(acc.w, dn, b.w), 0.f);
    *(float4*)(h1 + (size_t)n * 128 + lane * 4) = o;
}

__global__ __launch_bounds__(256)
void gather2_kernel(const __half* __restrict__ m2, float* __restrict__ out,
                    const int* __restrict__ row_ptr, const int* __restrict__ eidx,
                    const float* __restrict__ dis, const float* __restrict__ b2)
{
    int n = blockIdx.x * 8 + (threadIdx.x >> 5);
    if (n >= NN) return;
    int lane = threadIdx.x & 31;           // handles halves [lane*2, lane*2+2)

    int start = row_ptr[n];
    int end   = row_ptr[n + 1];
    float dn = dis[n];

    float2 mv = __half22float2(*(const __half2*)(m2 + (size_t)n * 64 + lane * 2));
    float2 acc;
    acc.x = dn * mv.x; acc.y = dn * mv.y;

    int e = start;
    for (; e + 4 <= end; e += 4) {
        int s0 = __ldg(eidx + e);
        int s1 = __ldg(eidx + e + 1);
        int s2 = __ldg(eidx + e + 2);
        int s3 = __ldg(eidx + e + 3);
        float d0 = __ldg(dis + s0), d1 = __ldg(dis + s1);
        float d2 = __ldg(dis + s2), d3 = __ldg(dis + s3);
        float2 v0 = __half22float2(*(const __half2*)(m2 + (size_t)s0 * 64 + lane * 2));
        float2 v1 = __half22float2(*(const __half2*)(m2 + (size_t)s1 * 64 + lane * 2));
        float2 v2 = __half22float2(*(const __half2*)(m2 + (size_t)s2 * 64 + lane * 2));
        float2 v3 = __half22float2(*(const __half2*)(m2 + (size_t)s3 * 64 + lane * 2));
        acc.x = fmaf(d0, v0.x, fmaf(d1, v1.x, fmaf(d2, v2.x, fmaf(d3, v3.x, acc.x))));
        acc.y = fmaf(d0, v0.y, fmaf(d1, v1.y, fmaf(d2, v2.y, fmaf(d3, v3.y, acc.y))));
    }
    for (; e < end; e++) {
        int s0 = __ldg(eidx + e);
        float d0 = __ldg(dis + s0);
        float2 v0 = __half22float2(*(const __half2*)(m2 + (size_t)s0 * 64 + lane * 2));
        acc.x = fmaf(d0, v0.x, acc.x);
        acc.y = fmaf(d0, v0.y, acc.y);
    }

    float2 b = *(const float2*)(b2 + lane * 2);
    float2 o;
    o.x = fmaf(acc.x, dn, b.x);
    o.y = fmaf(acc.y, dn, b.y);
    *(float2*)(out + (size_t)n * 64 + lane * 2) = o;
}

// ---------------------------------------------------------------------------
extern "C" void kernel_launch(void* const* d_in, const int* in_sizes, int n_in,
                              void* d_out, int out_size)
{
    void *pv;
    cudaGetSymbolAddress(&pv, g_hist);    int*    hist    = (int*)pv;
    cudaGetSymbolAddress(&pv, g_row_ptr); int*    row_ptr = (int*)pv;
    cudaGetSymbolAddress(&pv, g_cursor);  int*    cursor  = (int*)pv;
    cudaGetSymbolAddress(&pv, g_part);    int*    part    = (int*)pv;
    cudaGetSymbolAddress(&pv, g_eidx);    int*    eidx    = (int*)pv;
    cudaGetSymbolAddress(&pv, g_dis);     float*  dis     = (float*)pv;
    cudaGetSymbolAddress(&pv, g_m1h);     __half* m1      = (__half*)pv;
    cudaGetSymbolAddress(&pv, g_h1);      float*  h1      = (float*)pv;
    cudaGetSymbolAddress(&pv, g_m2h);     __half* m2      = (__half*)pv;
    cudaGetSymbolAddress(&pv, g_w1r);     float*  w1r     = (float*)pv;
    cudaGetSymbolAddress(&pv, g_w2r);     float*  w2r     = (float*)pv;

    const long long elems[6] = {38400000LL, 49152LL, 128LL, 8192LL, 64LL, 6400000LL};
    const long long bytesz[6] = {38400000LL*4, 49152LL*4, 128LL*4, 8192LL*4, 64LL*4, 6400000LL*4};
    const void* ptr[6] = {nullptr,nullptr,nullptr,nullptr,nullptr,nullptr};

    int matched = 0;
    for (int i = 0; i < n_in && i < 16; i++)
        for (int j = 0; j < 6; j++)
            if ((long long)in_sizes[i] == elems[j] && !ptr[j]) { ptr[j] = d_in[i]; matched++; break; }
    if (matched < 6) {
        for (int j = 0; j < 6; j++) ptr[j] = nullptr;
        matched = 0;
        for (int i = 0; i < n_in && i < 16; i++)
            for (int j = 0; j < 6; j++)
                if ((long long)in_sizes[i] == bytesz[j] && !ptr[j]) { ptr[j] = d_in[i]; matched++; break; }
    }
    if (matched < 6 && n_in >= 6)
        for (int j = 0; j < 6; j++) ptr[j] = d_in[j];

    const float* x  = (const float*)ptr[0];
    const float* W1 = (const float*)ptr[1];
    const float* b1 = (const float*)ptr[2];
    const float* W2 = (const float*)ptr[3];
    const float* b2 = (const float*)ptr[4];
    const int*   ei = (const int*)  ptr[5];
    const int* src = ei;
    const int* dst = ei + EE;
    float* out = (float*)d_out;

    const int smem1 = 3 * (128 * 20 + 16 * 136) * 4;   // 56832 B
    const int smem2 = 3 * (128 * 20 + 16 * 72) * 4;    // 44544 B
    cudaFuncSetAttribute(gemm_tf32_async<128>,
                         cudaFuncAttributeMaxDynamicSharedMemorySize, smem1);
    cudaFuncSetAttribute(gemm_tf32_async<64>,
                         cudaFuncAttributeMaxDynamicSharedMemorySize, smem2);

    const bool fork = (g_side && g_ev_fork && g_ev_join);
    cudaStream_t s_csr = fork ? g_side : (cudaStream_t)0;

    if (fork) {
        cudaEventRecord(g_ev_fork, 0);
        cudaStreamWaitEvent(g_side, g_ev_fork, 0);
    }

    // CSR on side stream; gemm1 is the 4th launch (profiler slot).
    zero_hist_kernel<<<(NN + 255) / 256, 256, 0, s_csr>>>(hist);
    hist_kernel     <<<(EE + 255) / 256, 256, 0, s_csr>>>(dst, hist);

    round_w_kernel<<<(384 * 128 + 255) / 256, 256>>>(W1, W2, w1r, w2r);
    gemm_tf32_async<128><<<(NN + 127) / 128, 256, smem1>>>(x, w1r, m1, NN, 384);

    scan1_kernel    <<<SCAN_BLOCKS, 1024, 0, s_csr>>>(hist, row_ptr, part);
    scan2_kernel    <<<1, 128, 0, s_csr>>>(part, row_ptr);
    scan3_kernel    <<<SCAN_BLOCKS, 1024, 0, s_csr>>>(row_ptr, part, hist, cursor, dis);
    place_kernel    <<<(EE + 255) / 256, 256, 0, s_csr>>>(src, dst, cursor, eidx);
    if (fork) cudaEventRecord(g_ev_join, g_side);

    if (fork) cudaStreamWaitEvent((cudaStream_t)0, g_ev_join, 0);

    gather1_kernel<<<(NN + 7) / 8, 256>>>(m1, h1, row_ptr, eidx, dis, b1);

    gemm_tf32_async<64><<<(NN + 127) / 128, 256, smem2>>>(h1, w2r, m2, NN, 128);

    gather2_kernel<<<(NN + 7) / 8, 256>>>(m2, out, row_ptr, eidx, dis, b2);
}

// round 16
// speedup vs baseline: 1.8448x; 1.0959x over previous
#include <cuda_runtime.h>
#include <cuda_fp16.h>
#include <cstdint>

// 2-layer GCN, N=100000, E=3200000, 384 -> 128 -> 64.
// TF32 tensor-core GEMMs (cp.async); messages stored fp16 PRE-SCALED by dis
// (msg = dis*m), so gathers are pure row sums (no per-edge dis load/FMA chain):
//   h1 = relu(dis[n]*(msg1[n] + sum msg1[s]) + b1)
//   out =      dis[n]*(msg2[n] + sum msg2[s]) + b2
// gemm2 folds dis into its epilogue; msg1 scaled by a tiny kernel post-join.
// All __device__ buffers via cudaGetSymbolAddress (GB300/ATS host-shadow trap).

#define NN 100000
#define EE 3200000
#define SCAN_BLOCKS 98   // ceil(100000/1024)

__device__ int   g_hist[NN];
__device__ int   g_row_ptr[NN + 1];
__device__ int   g_cursor[NN];
__device__ int   g_part[SCAN_BLOCKS];
__device__ int   g_eidx[EE];
__device__ float g_dis[NN];
__device__ __align__(16) __half g_m1h[NN * 128];
__device__ __align__(16) float  g_h1[NN * 128];
__device__ __align__(16) __half g_m2h[NN * 64];
__device__ __align__(16) float  g_w1r[384 * 128];
__device__ __align__(16) float  g_w2r[128 * 64];

namespace {
cudaStream_t g_side = nullptr;
cudaEvent_t  g_ev_fork = nullptr, g_ev_join = nullptr;
struct Init {
    Init() {
        if (cudaStreamCreateWithFlags(&g_side, cudaStreamNonBlocking) != cudaSuccess)
            g_side = nullptr;
        if (cudaEventCreateWithFlags(&g_ev_fork, cudaEventDisableTiming) != cudaSuccess)
            g_ev_fork = nullptr;
        if (cudaEventCreateWithFlags(&g_ev_join, cudaEventDisableTiming) != cudaSuccess)
            g_ev_join = nullptr;
    }
};
static Init s_init;
}

__device__ __forceinline__ float f2tf32(float x) {
    uint32_t u;
    asm("cvt.rna.tf32.f32 %0, %1;" : "=r"(u) : "f"(x));
    return __uint_as_float(u);
}
__device__ __forceinline__ uint32_t f2tf32_bits(float x) {
    uint32_t u;
    asm("cvt.rna.tf32.f32 %0, %1;" : "=r"(u) : "f"(x));
    return u;
}
__device__ __forceinline__ float4 h4_to_f4(uint2 r) {
    __half2 a = *(__half2*)&r.x;
    __half2 b = *(__half2*)&r.y;
    float2 fa = __half22float2(a);
    float2 fb = __half22float2(b);
    return make_float4(fa.x, fa.y, fb.x, fb.y);
}

// ---------------------------------------------------------------------------
// CSR build
// ---------------------------------------------------------------------------
__global__ void zero_hist_kernel(int* __restrict__ hist) {
    int i = blockIdx.x * 256 + threadIdx.x;
    if (i < NN) hist[i] = 0;
}

__global__ void hist_kernel(const int* __restrict__ dst, int* __restrict__ hist) {
    int e = blockIdx.x * 256 + threadIdx.x;
    if (e < EE) atomicAdd(&hist[dst[e]], 1);
}

__global__ void scan1_kernel(const int* __restrict__ hist, int* __restrict__ row_ptr,
                             int* __restrict__ part)
{
    int gi = blockIdx.x * 1024 + threadIdx.x;
    int v = (gi < NN) ? hist[gi] : 0;
    int lane = threadIdx.x & 31, wid = threadIdx.x >> 5;

    int x = v;
#pragma unroll
    for (int o = 1; o < 32; o <<= 1) {
        int t = __shfl_up_sync(0xffffffffu, x, o);
        if (lane >= o) x += t;
    }
    __shared__ int wsum[32];
    if (lane == 31) wsum[wid] = x;
    __syncthreads();
    if (wid == 0) {
        int y = wsum[lane];
#pragma unroll
        for (int o = 1; o < 32; o <<= 1) {
            int t = __shfl_up_sync(0xffffffffu, y, o);
            if (lane >= o) y += t;
        }
        wsum[lane] = y;
    }
    __syncthreads();
    int incl = x + (wid ? wsum[wid - 1] : 0);
    if (gi < NN) row_ptr[gi] = incl - v;
    if (threadIdx.x == 1023) part[blockIdx.x] = incl;
}

__global__ void scan2_kernel(int* __restrict__ part, int* __restrict__ row_ptr)
{
    int lane = threadIdx.x & 31, wid = threadIdx.x >> 5;
    int v = (threadIdx.x < SCAN_BLOCKS) ? part[threadIdx.x] : 0;
    int x = v;
#pragma unroll
    for (int o = 1; o < 32; o <<= 1) {
        int t = __shfl_up_sync(0xffffffffu, x, o);
        if (lane >= o) x += t;
    }
    __shared__ int ws[4];
    if (lane == 31) ws[wid] = x;
    __syncthreads();
    int add = 0;
    for (int w = 0; w < wid; w++) add += ws[w];
    int incl = x + add;
    if (threadIdx.x < SCAN_BLOCKS) part[threadIdx.x] = incl - v;
    if (threadIdx.x == SCAN_BLOCKS - 1) row_ptr[NN] = incl;
}

__global__ void scan3_kernel(int* __restrict__ row_ptr, const int* __restrict__ part,
                             const int* __restrict__ hist, int* __restrict__ cursor,
                             float* __restrict__ dis)
{
    int i = blockIdx.x * 1024 + threadIdx.x;
    if (i < NN) {
        int rp = row_ptr[i] + part[blockIdx.x];
        row_ptr[i] = rp;
        cursor[i] = rp;
        dis[i] = rsqrtf((float)(hist[i] + 1));
    }
}

__global__ void place_kernel(const int* __restrict__ src, const int* __restrict__ dst,
                             int* __restrict__ cursor, int* __restrict__ eidx) {
    int e = blockIdx.x * 256 + threadIdx.x;
    if (e >= EE) return;
    int d = dst[e];
    int slot = atomicAdd(&cursor[d], 1);
    eidx[slot] = src[e];
}

// Pre-round weights to tf32 (RNA).
__global__ void round_w_kernel(const float* __restrict__ w1, const float* __restrict__ w2,
                               float* __restrict__ w1r, float* __restrict__ w2r)
{
    int i = blockIdx.x * 256 + threadIdx.x;
    if (i < 384 * 128) w1r[i] = f2tf32(w1[i]);
    if (i < 128 * 64)  w2r[i] = f2tf32(w2[i]);
}

// In-place scale of fp16 message rows by dis[row]: msg1 = dis * m1.
__global__ void scale_m1_kernel(__half* __restrict__ m1, const float* __restrict__ dis)
{
    int i = blockIdx.x * 256 + threadIdx.x;        // uint2 = 4 halves
    if (i >= NN * 32) return;
    int row = i >> 5;
    float d = dis[row];
    uint2 r = *(uint2*)(m1 + (size_t)i * 4);
    float4 v = h4_to_f4(r);
    __half2 lo = __floats2half2_rn(v.x * d, v.y * d);
    __half2 hi = __floats2half2_rn(v.z * d, v.w * d);
    uint2 o; o.x = *(uint32_t*)&lo; o.y = *(uint32_t*)&hi;
    *(uint2*)(m1 + (size_t)i * 4) = o;
}

// ---------------------------------------------------------------------------
// TF32 tensor-core GEMM, cp.async 3-stage pipeline, fp16 output,
// optional per-row scale (rowscale != nullptr => m = rowscale[row]*(A@W)).
// ---------------------------------------------------------------------------
template<int BN>
__global__ __launch_bounds__(256)
void gemm_tf32_async(const float* __restrict__ A, const float* __restrict__ W,
                     __half* __restrict__ m, const float* __restrict__ rowscale,
                     int M, int K)
{
    constexpr int BM = 128, BK = 16, S = 3;
    constexpr int NFRAG = BN / 16;
    constexpr int ASTR = 20;
    constexpr int BSTR = BN + 8;
    constexpr int ASZ = BM * ASTR;
    constexpr int BSZ = BK * BSTR;
    constexpr int BCH = BK * BN / 4;
    constexpr int BPT = (BCH + 255) / 256;

    extern __shared__ float smem[];
    float* As = smem;
    float* Bs = smem + S * ASZ;

    const int tid = threadIdx.x;
    const int wid = tid >> 5, lane = tid & 31;
    const int gID = lane >> 2;
    const int tig = lane & 3;
    const int wm = (wid & 3) * 32;
    const int wn = (wid >> 2) * (BN / 2);
    const int row0 = blockIdx.x * BM;

    float c[2][NFRAG][4];
#pragma unroll
    for (int i = 0; i < 2; i++)
#pragma unroll
        for (int j = 0; j < NFRAG; j++)
#pragma unroll
            for (int q = 0; q < 4; q++) c[i][j][q] = 0.0f;

    auto issue_tile = [&](int kt, int stg) {
#pragma unroll
        for (int p = 0; p < 2; p++) {
            int i = tid + p * 256;
            int r = i >> 2;
            int cc = (i & 3) * 4;
            int gr = row0 + r;
            int sz = (gr < M) ? 16 : 0;
            if (gr >= M) gr = M - 1;
            const float* g = A + (size_t)gr * K + kt + cc;
            uint32_t s = (uint32_t)__cvta_generic_to_shared(
                &As[stg * ASZ + r * ASTR + cc]);
            asm volatile("cp.async.cg.shared.global [%0], [%1], 16, %2;"
                         :: "r"(s), "l"(g), "r"(sz));
        }
#pragma unroll
        for (int p = 0; p < BPT; p++) {
            int i = tid + p * 256;
            if (i < BCH) {
                int r  = i / (BN / 4);
                int cc = (i % (BN / 4)) * 4;
                const float* g = W + (size_t)(kt + r) * BN + cc;
                uint32_t s = (uint32_t)__cvta_generic_to_shared(
                    &Bs[stg * BSZ + r * BSTR + cc]);
                asm volatile("cp.async.cg.shared.global [%0], [%1], 16, %2;"
                             :: "r"(s), "l"(g), "r"(16));
            }
        }
    };

    auto compute = [&](int buf) {
        const float* a = As + buf * ASZ;
        const float* b = Bs + buf * BSZ;
#pragma unroll
        for (int ks = 0; ks < 2; ks++) {
            const int k0 = ks * 8;
            uint32_t af[2][4];
#pragma unroll
            for (int i = 0; i < 2; i++) {
                int mi = wm + i * 16 + gID;
                af[i][0] = f2tf32_bits(a[(mi    ) * ASTR + k0 + tig    ]);
                af[i][1] = f2tf32_bits(a[(mi + 8) * ASTR + k0 + tig    ]);
                af[i][2] = f2tf32_bits(a[(mi    ) * ASTR + k0 + tig + 4]);
                af[i][3] = f2tf32_bits(a[(mi + 8) * ASTR + k0 + tig + 4]);
            }
            uint32_t bf[NFRAG][2];
#pragma unroll
            for (int j = 0; j < NFRAG; j++) {
                int nj = wn + j * 8 + gID;
                bf[j][0] = __float_as_uint(b[(k0 + tig    ) * BSTR + nj]);
                bf[j][1] = __float_as_uint(b[(k0 + tig + 4) * BSTR + nj]);
            }
#pragma unroll
            for (int i = 0; i < 2; i++)
#pragma unroll
                for (int j = 0; j < NFRAG; j++) {
                    asm volatile(
                        "mma.sync.aligned.m16n8k8.row.col.f32.tf32.tf32.f32 "
                        "{%0,%1,%2,%3}, {%4,%5,%6,%7}, {%8,%9}, {%0,%1,%2,%3};"
                        : "+f"(c[i][j][0]), "+f"(c[i][j][1]),
                          "+f"(c[i][j][2]), "+f"(c[i][j][3])
                        : "r"(af[i][0]), "r"(af[i][1]), "r"(af[i][2]), "r"(af[i][3]),
                          "r"(bf[j][0]), "r"(bf[j][1]));
                }
        }
    };

    const int T = K / BK;
#pragma unroll
    for (int s = 0; s < S - 1; s++) {
        if (s < T) issue_tile(s * BK, s);
        asm volatile("cp.async.commit_group;" ::: "memory");
    }

    for (int t = 0; t < T; t++) {
        asm volatile("cp.async.wait_group 1;" ::: "memory");
        __syncthreads();
        int tn = t + S - 1;
        if (tn < T) issue_tile(tn * BK, tn % S);
        asm volatile("cp.async.commit_group;" ::: "memory");
        compute(t % S);
    }

#pragma unroll
    for (int i = 0; i < 2; i++) {
#pragma unroll
        for (int j = 0; j < NFRAG; j++) {
            int gcol = wn + j * 8 + 2 * tig;
            int grow0 = row0 + wm + i * 16 + gID;
            int grow1 = grow0 + 8;
            float s0 = 1.f, s1 = 1.f;
            if (rowscale) {
                if (grow0 < M) s0 = rowscale[grow0];
                if (grow1 < M) s1 = rowscale[grow1];
            }
            if (grow0 < M)
                *(__half2*)(m + (size_t)grow0 * BN + gcol) =
                    __floats2half2_rn(c[i][j][0] * s0, c[i][j][1] * s0);
            if (grow1 < M)
                *(__half2*)(m + (size_t)grow1 * BN + gcol) =
                    __floats2half2_rn(c[i][j][2] * s1, c[i][j][3] * s1);
        }
    }
}

// ---------------------------------------------------------------------------
// Gather: pure row sums of pre-scaled fp16 messages. Warp per node, 8x unroll.
// ---------------------------------------------------------------------------
__global__ __launch_bounds__(256)
void gather1_kernel(const __half* __restrict__ m1, float* __restrict__ h1,
                    const int* __restrict__ row_ptr, const int* __restrict__ eidx,
                    const float* __restrict__ dis, const float* __restrict__ b1)
{
    int n = blockIdx.x * 8 + (threadIdx.x >> 5);
    if (n >= NN) return;
    int lane = threadIdx.x & 31;          // halves [lane*4, lane*4+4)

    int start = row_ptr[n];
    int end   = row_ptr[n + 1];

    float4 acc = h4_to_f4(*(const uint2*)(m1 + (size_t)n * 128 + lane * 4));  // self

    int e = start;
    for (; e + 8 <= end; e += 8) {
        float4 v[8];
#pragma unroll
        for (int q = 0; q < 8; q++) {
            int s = __ldg(eidx + e + q);
            v[q] = h4_to_f4(*(const uint2*)(m1 + (size_t)s * 128 + lane * 4));
        }
#pragma unroll
        for (int q = 0; q < 8; q++) {
            acc.x += v[q].x; acc.y += v[q].y; acc.z += v[q].z; acc.w += v[q].w;
        }
    }
    for (; e < end; e++) {
        int s = __ldg(eidx + e);
        float4 v = h4_to_f4(*(const uint2*)(m1 + (size_t)s * 128 + lane * 4));
        acc.x += v.x; acc.y += v.y; acc.z += v.z; acc.w += v.w;
    }

    float dn = dis[n];
    float4 b = *(const float4*)(b1 + lane * 4);
    float4 o;
    o.x = fmaxf(fmaf(acc.x, dn, b.x), 0.f);
    o.y = fmaxf(fmaf(acc.y, dn, b.y), 0.f);
    o.z = fmaxf(fmaf(acc.z, dn, b.z), 0.f);
    o.w = fmaxf(fmaf(acc.w, dn, b.w), 0.f);
    *(float4*)(h1 + (size_t)n * 128 + lane * 4) = o;
}

__global__ __launch_bounds__(256)
void gather2_kernel(const __half* __restrict__ m2, float* __restrict__ out,
                    const int* __restrict__ row_ptr, const int* __restrict__ eidx,
                    const float* __restrict__ dis, const float* __restrict__ b2)
{
    int n = blockIdx.x * 8 + (threadIdx.x >> 5);
    if (n >= NN) return;
    int lane = threadIdx.x & 31;          // halves [lane*2, lane*2+2)

    int start = row_ptr[n];
    int end   = row_ptr[n + 1];

    float2 acc = __half22float2(*(const __half2*)(m2 + (size_t)n * 64 + lane * 2));

    int e = start;
    for (; e + 8 <= end; e += 8) {
        float2 v[8];
#pragma unroll
        for (int q = 0; q < 8; q++) {
            int s = __ldg(eidx + e + q);
            v[q] = __half22float2(*(const __half2*)(m2 + (size_t)s * 64 + lane * 2));
        }
#pragma unroll
        for (int q = 0; q < 8; q++) { acc.x += v[q].x; acc.y += v[q].y; }
    }
    for (; e < end; e++) {
        int s = __ldg(eidx + e);
        float2 v = __half22float2(*(const __half2*)(m2 + (size_t)s * 64 + lane * 2));
        acc.x += v.x; acc.y += v.y;
    }

    float dn = dis[n];
    float2 b = *(const float2*)(b2 + lane * 2);
    float2 o;
    o.x = fmaf(acc.x, dn, b.x);
    o.y = fmaf(acc.y, dn, b.y);
    *(float2*)(out + (size_t)n * 64 + lane * 2) = o;
}

// ---------------------------------------------------------------------------
extern "C" void kernel_launch(void* const* d_in, const int* in_sizes, int n_in,
                              void* d_out, int out_size)
{
    void *pv;
    cudaGetSymbolAddress(&pv, g_hist);    int*    hist    = (int*)pv;
    cudaGetSymbolAddress(&pv, g_row_ptr); int*    row_ptr = (int*)pv;
    cudaGetSymbolAddress(&pv, g_cursor);  int*    cursor  = (int*)pv;
    cudaGetSymbolAddress(&pv, g_part);    int*    part    = (int*)pv;
    cudaGetSymbolAddress(&pv, g_eidx);    int*    eidx    = (int*)pv;
    cudaGetSymbolAddress(&pv, g_dis);     float*  dis     = (float*)pv;
    cudaGetSymbolAddress(&pv, g_m1h);     __half* m1      = (__half*)pv;
    cudaGetSymbolAddress(&pv, g_h1);      float*  h1      = (float*)pv;
    cudaGetSymbolAddress(&pv, g_m2h);     __half* m2      = (__half*)pv;
    cudaGetSymbolAddress(&pv, g_w1r);     float*  w1r     = (float*)pv;
    cudaGetSymbolAddress(&pv, g_w2r);     float*  w2r     = (float*)pv;

    const long long elems[6] = {38400000LL, 49152LL, 128LL, 8192LL, 64LL, 6400000LL};
    const long long bytesz[6] = {38400000LL*4, 49152LL*4, 128LL*4, 8192LL*4, 64LL*4, 6400000LL*4};
    const void* ptr[6] = {nullptr,nullptr,nullptr,nullptr,nullptr,nullptr};

    int matched = 0;
    for (int i = 0; i < n_in && i < 16; i++)
        for (int j = 0; j < 6; j++)
            if ((long long)in_sizes[i] == elems[j] && !ptr[j]) { ptr[j] = d_in[i]; matched++; break; }
    if (matched < 6) {
        for (int j = 0; j < 6; j++) ptr[j] = nullptr;
        matched = 0;
        for (int i = 0; i < n_in && i < 16; i++)
            for (int j = 0; j < 6; j++)
                if ((long long)in_sizes[i] == bytesz[j] && !ptr[j]) { ptr[j] = d_in[i]; matched++; break; }
    }
    if (matched < 6 && n_in >= 6)
        for (int j = 0; j < 6; j++) ptr[j] = d_in[j];

    const float* x  = (const float*)ptr[0];
    const float* W1 = (const float*)ptr[1];
    const float* b1 = (const float*)ptr[2];
    const float* W2 = (const float*)ptr[3];
    const float* b2 = (const float*)ptr[4];
    const int*   ei = (const int*)  ptr[5];
    const int* src = ei;
    const int* dst = ei + EE;
    float* out = (float*)d_out;

    const int smem1 = 3 * (128 * 20 + 16 * 136) * 4;   // 56832 B
    const int smem2 = 3 * (128 * 20 + 16 * 72) * 4;    // 44544 B
    cudaFuncSetAttribute(gemm_tf32_async<128>,
                         cudaFuncAttributeMaxDynamicSharedMemorySize, smem1);
    cudaFuncSetAttribute(gemm_tf32_async<64>,
                         cudaFuncAttributeMaxDynamicSharedMemorySize, smem2);

    const bool fork = (g_side && g_ev_fork && g_ev_join);
    cudaStream_t s_csr = fork ? g_side : (cudaStream_t)0;

    if (fork) {
        cudaEventRecord(g_ev_fork, 0);
        cudaStreamWaitEvent(g_side, g_ev_fork, 0);
    }

    // CSR on side stream; gemm1 is the 4th launch (profiler slot).
    zero_hist_kernel<<<(NN + 255) / 256, 256, 0, s_csr>>>(hist);
    hist_kernel     <<<(EE + 255) / 256, 256, 0, s_csr>>>(dst, hist);

    round_w_kernel<<<(384 * 128 + 255) / 256, 256>>>(W1, W2, w1r, w2r);
    gemm_tf32_async<128><<<(NN + 127) / 128, 256, smem1>>>(x, w1r, m1, nullptr, NN, 384);

    scan1_kernel    <<<SCAN_BLOCKS, 1024, 0, s_csr>>>(hist, row_ptr, part);
    scan2_kernel    <<<1, 128, 0, s_csr>>>(part, row_ptr);
    scan3_kernel    <<<SCAN_BLOCKS, 1024, 0, s_csr>>>(row_ptr, part, hist, cursor, dis);
    place_kernel    <<<(EE + 255) / 256, 256, 0, s_csr>>>(src, dst, cursor, eidx);
    if (fork) cudaEventRecord(g_ev_join, g_side);

    if (fork) cudaStreamWaitEvent((cudaStream_t)0, g_ev_join, 0);

    // msg1 = dis * m1 (in place), then pure-sum gathers.
    scale_m1_kernel<<<(NN * 32 + 255) / 256, 256>>>(m1, dis);
    gather1_kernel<<<(NN + 7) / 8, 256>>>(m1, h1, row_ptr, eidx, dis, b1);

    // gemm2 folds dis into epilogue: msg2 = dis * (h1 @ W2).
    gemm_tf32_async<64><<<(NN + 127) / 128, 256, smem2>>>(h1, w2r, m2, dis, NN, 128);

    gather2_kernel<<<(NN + 7) / 8, 256>>>(m2, out, row_ptr, eidx, dis, b2);
}

// round 17
// speedup vs baseline: 1.9153x; 1.0382x over previous
#include <cuda_runtime.h>
#include <cuda_fp16.h>
#include <cstdint>

// 2-layer GCN, N=100000, E=3200000, 384 -> 128 -> 64.
// TF32 GEMMs (cp.async, 4-stage); fp16 messages pre-scaled by dis; gathers are
// pure row sums with 16B loads: gather1 = half-warp/node, gather2 = 8 lanes/node.
// All __device__ buffers via cudaGetSymbolAddress (GB300/ATS host-shadow trap).

#define NN 100000
#define EE 3200000
#define SCAN_BLOCKS 98   // ceil(100000/1024)

__device__ int   g_hist[NN];
__device__ int   g_row_ptr[NN + 1];
__device__ int   g_cursor[NN];
__device__ int   g_part[SCAN_BLOCKS];
__device__ int   g_eidx[EE];
__device__ float g_dis[NN];
__device__ __align__(16) __half g_m1h[NN * 128];
__device__ __align__(16) float  g_h1[NN * 128];
__device__ __align__(16) __half g_m2h[NN * 64];
__device__ __align__(16) float  g_w1r[384 * 128];
__device__ __align__(16) float  g_w2r[128 * 64];

namespace {
cudaStream_t g_side = nullptr;
cudaEvent_t  g_ev_fork = nullptr, g_ev_join = nullptr;
struct Init {
    Init() {
        if (cudaStreamCreateWithFlags(&g_side, cudaStreamNonBlocking) != cudaSuccess)
            g_side = nullptr;
        if (cudaEventCreateWithFlags(&g_ev_fork, cudaEventDisableTiming) != cudaSuccess)
            g_ev_fork = nullptr;
        if (cudaEventCreateWithFlags(&g_ev_join, cudaEventDisableTiming) != cudaSuccess)
            g_ev_join = nullptr;
    }
};
static Init s_init;
}

__device__ __forceinline__ float f2tf32(float x) {
    uint32_t u;
    asm("cvt.rna.tf32.f32 %0, %1;" : "=r"(u) : "f"(x));
    return __uint_as_float(u);
}
__device__ __forceinline__ uint32_t f2tf32_bits(float x) {
    uint32_t u;
    asm("cvt.rna.tf32.f32 %0, %1;" : "=r"(u) : "f"(x));
    return u;
}
__device__ __forceinline__ float4 h4_to_f4(uint2 r) {
    __half2 a = *(__half2*)&r.x;
    __half2 b = *(__half2*)&r.y;
    float2 fa = __half22float2(a);
    float2 fb = __half22float2(b);
    return make_float4(fa.x, fa.y, fb.x, fb.y);
}
// accumulate 8 halves (uint4) into acc[0..8)
__device__ __forceinline__ void h8_acc(uint4 r, float* acc) {
    const __half2* h = (const __half2*)&r;
#pragma unroll
    for (int k = 0; k < 4; k++) {
        float2 f = __half22float2(h[k]);
        acc[2 * k]     += f.x;
        acc[2 * k + 1] += f.y;
    }
}

// ---------------------------------------------------------------------------
// CSR build
// ---------------------------------------------------------------------------
__global__ void zero_hist_kernel(int* __restrict__ hist) {
    int i = blockIdx.x * 256 + threadIdx.x;
    if (i < NN) hist[i] = 0;
}

__global__ void hist_kernel(const int* __restrict__ dst, int* __restrict__ hist) {
    int e = blockIdx.x * 256 + threadIdx.x;
    if (e < EE) atomicAdd(&hist[dst[e]], 1);
}

__global__ void scan1_kernel(const int* __restrict__ hist, int* __restrict__ row_ptr,
                             int* __restrict__ part)
{
    int gi = blockIdx.x * 1024 + threadIdx.x;
    int v = (gi < NN) ? hist[gi] : 0;
    int lane = threadIdx.x & 31, wid = threadIdx.x >> 5;

    int x = v;
#pragma unroll
    for (int o = 1; o < 32; o <<= 1) {
        int t = __shfl_up_sync(0xffffffffu, x, o);
        if (lane >= o) x += t;
    }
    __shared__ int wsum[32];
    if (lane == 31) wsum[wid] = x;
    __syncthreads();
    if (wid == 0) {
        int y = wsum[lane];
#pragma unroll
        for (int o = 1; o < 32; o <<= 1) {
            int t = __shfl_up_sync(0xffffffffu, y, o);
            if (lane >= o) y += t;
        }
        wsum[lane] = y;
    }
    __syncthreads();
    int incl = x + (wid ? wsum[wid - 1] : 0);
    if (gi < NN) row_ptr[gi] = incl - v;
    if (threadIdx.x == 1023) part[blockIdx.x] = incl;
}

__global__ void scan2_kernel(int* __restrict__ part, int* __restrict__ row_ptr)
{
    int lane = threadIdx.x & 31, wid = threadIdx.x >> 5;
    int v = (threadIdx.x < SCAN_BLOCKS) ? part[threadIdx.x] : 0;
    int x = v;
#pragma unroll
    for (int o = 1; o < 32; o <<= 1) {
        int t = __shfl_up_sync(0xffffffffu, x, o);
        if (lane >= o) x += t;
    }
    __shared__ int ws[4];
    if (lane == 31) ws[wid] = x;
    __syncthreads();
    int add = 0;
    for (int w = 0; w < wid; w++) add += ws[w];
    int incl = x + add;
    if (threadIdx.x < SCAN_BLOCKS) part[threadIdx.x] = incl - v;
    if (threadIdx.x == SCAN_BLOCKS - 1) row_ptr[NN] = incl;
}

__global__ void scan3_kernel(int* __restrict__ row_ptr, const int* __restrict__ part,
                             const int* __restrict__ hist, int* __restrict__ cursor,
                             float* __restrict__ dis)
{
    int i = blockIdx.x * 1024 + threadIdx.x;
    if (i < NN) {
        int rp = row_ptr[i] + part[blockIdx.x];
        row_ptr[i] = rp;
        cursor[i] = rp;
        dis[i] = rsqrtf((float)(hist[i] + 1));
    }
}

__global__ void place_kernel(const int* __restrict__ src, const int* __restrict__ dst,
                             int* __restrict__ cursor, int* __restrict__ eidx) {
    int e = blockIdx.x * 256 + threadIdx.x;
    if (e >= EE) return;
    int d = dst[e];
    int slot = atomicAdd(&cursor[d], 1);
    eidx[slot] = src[e];
}

__global__ void round_w_kernel(const float* __restrict__ w1, const float* __restrict__ w2,
                               float* __restrict__ w1r, float* __restrict__ w2r)
{
    int i = blockIdx.x * 256 + threadIdx.x;
    if (i < 384 * 128) w1r[i] = f2tf32(w1[i]);
    if (i < 128 * 64)  w2r[i] = f2tf32(w2[i]);
}

// In-place scale of fp16 message rows by dis[row]: msg1 = dis * m1.
__global__ void scale_m1_kernel(__half* __restrict__ m1, const float* __restrict__ dis)
{
    int i = blockIdx.x * 256 + threadIdx.x;        // uint2 = 4 halves
    if (i >= NN * 32) return;
    int row = i >> 5;
    float d = dis[row];
    uint2 r = *(uint2*)(m1 + (size_t)i * 4);
    float4 v = h4_to_f4(r);
    __half2 lo = __floats2half2_rn(v.x * d, v.y * d);
    __half2 hi = __floats2half2_rn(v.z * d, v.w * d);
    uint2 o; o.x = *(uint32_t*)&lo; o.y = *(uint32_t*)&hi;
    *(uint2*)(m1 + (size_t)i * 4) = o;
}

// ---------------------------------------------------------------------------
// TF32 tensor-core GEMM, cp.async 4-stage pipeline, fp16 output,
// optional per-row scale.
// ---------------------------------------------------------------------------
template<int BN>
__global__ __launch_bounds__(256)
void gemm_tf32_async(const float* __restrict__ A, const float* __restrict__ W,
                     __half* __restrict__ m, const float* __restrict__ rowscale,
                     int M, int K)
{
    constexpr int BM = 128, BK = 16, S = 4;
    constexpr int NFRAG = BN / 16;
    constexpr int ASTR = 20;
    constexpr int BSTR = BN + 8;
    constexpr int ASZ = BM * ASTR;
    constexpr int BSZ = BK * BSTR;
    constexpr int BCH = BK * BN / 4;
    constexpr int BPT = (BCH + 255) / 256;

    extern __shared__ float smem[];
    float* As = smem;
    float* Bs = smem + S * ASZ;

    const int tid = threadIdx.x;
    const int wid = tid >> 5, lane = tid & 31;
    const int gID = lane >> 2;
    const int tig = lane & 3;
    const int wm = (wid & 3) * 32;
    const int wn = (wid >> 2) * (BN / 2);
    const int row0 = blockIdx.x * BM;

    float c[2][NFRAG][4];
#pragma unroll
    for (int i = 0; i < 2; i++)
#pragma unroll
        for (int j = 0; j < NFRAG; j++)
#pragma unroll
            for (int q = 0; q < 4; q++) c[i][j][q] = 0.0f;

    auto issue_tile = [&](int kt, int stg) {
#pragma unroll
        for (int p = 0; p < 2; p++) {
            int i = tid + p * 256;
            int r = i >> 2;
            int cc = (i & 3) * 4;
            int gr = row0 + r;
            int sz = (gr < M) ? 16 : 0;
            if (gr >= M) gr = M - 1;
            const float* g = A + (size_t)gr * K + kt + cc;
            uint32_t s = (uint32_t)__cvta_generic_to_shared(
                &As[stg * ASZ + r * ASTR + cc]);
            asm volatile("cp.async.cg.shared.global [%0], [%1], 16, %2;"
                         :: "r"(s), "l"(g), "r"(sz));
        }
#pragma unroll
        for (int p = 0; p < BPT; p++) {
            int i = tid + p * 256;
            if (i < BCH) {
                int r  = i / (BN / 4);
                int cc = (i % (BN / 4)) * 4;
                const float* g = W + (size_t)(kt + r) * BN + cc;
                uint32_t s = (uint32_t)__cvta_generic_to_shared(
                    &Bs[stg * BSZ + r * BSTR + cc]);
                asm volatile("cp.async.cg.shared.global [%0], [%1], 16, %2;"
                             :: "r"(s), "l"(g), "r"(16));
            }
        }
    };

    auto compute = [&](int buf) {
        const float* a = As + buf * ASZ;
        const float* b = Bs + buf * BSZ;
#pragma unroll
        for (int ks = 0; ks < 2; ks++) {
            const int k0 = ks * 8;
            uint32_t af[2][4];
#pragma unroll
            for (int i = 0; i < 2; i++) {
                int mi = wm + i * 16 + gID;
                af[i][0] = f2tf32_bits(a[(mi    ) * ASTR + k0 + tig    ]);
                af[i][1] = f2tf32_bits(a[(mi + 8) * ASTR + k0 + tig    ]);
                af[i][2] = f2tf32_bits(a[(mi    ) * ASTR + k0 + tig + 4]);
                af[i][3] = f2tf32_bits(a[(mi + 8) * ASTR + k0 + tig + 4]);
            }
            uint32_t bf[NFRAG][2];
#pragma unroll
            for (int j = 0; j < NFRAG; j++) {
                int nj = wn + j * 8 + gID;
                bf[j][0] = __float_as_uint(b[(k0 + tig    ) * BSTR + nj]);
                bf[j][1] = __float_as_uint(b[(k0 + tig + 4) * BSTR + nj]);
            }
#pragma unroll
            for (int i = 0; i < 2; i++)
#pragma unroll
                for (int j = 0; j < NFRAG; j++) {
                    asm volatile(
                        "mma.sync.aligned.m16n8k8.row.col.f32.tf32.tf32.f32 "
                        "{%0,%1,%2,%3}, {%4,%5,%6,%7}, {%8,%9}, {%0,%1,%2,%3};"
                        : "+f"(c[i][j][0]), "+f"(c[i][j][1]),
                          "+f"(c[i][j][2]), "+f"(c[i][j][3])
                        : "r"(af[i][0]), "r"(af[i][1]), "r"(af[i][2]), "r"(af[i][3]),
                          "r"(bf[j][0]), "r"(bf[j][1]));
                }
        }
    };

    const int T = K / BK;
#pragma unroll
    for (int s = 0; s < S - 1; s++) {
        if (s < T) issue_tile(s * BK, s);
        asm volatile("cp.async.commit_group;" ::: "memory");
    }

    for (int t = 0; t < T; t++) {
        asm volatile("cp.async.wait_group 2;" ::: "memory");   // S-2 == 2
        __syncthreads();
        int tn = t + S - 1;
        if (tn < T) issue_tile(tn * BK, tn % S);
        asm volatile("cp.async.commit_group;" ::: "memory");
        compute(t % S);
    }

#pragma unroll
    for (int i = 0; i < 2; i++) {
#pragma unroll
        for (int j = 0; j < NFRAG; j++) {
            int gcol = wn + j * 8 + 2 * tig;
            int grow0 = row0 + wm + i * 16 + gID;
            int grow1 = grow0 + 8;
            float s0 = 1.f, s1 = 1.f;
            if (rowscale) {
                if (grow0 < M) s0 = rowscale[grow0];
                if (grow1 < M) s1 = rowscale[grow1];
            }
            if (grow0 < M)
                *(__half2*)(m + (size_t)grow0 * BN + gcol) =
                    __floats2half2_rn(c[i][j][0] * s0, c[i][j][1] * s0);
            if (grow1 < M)
                *(__half2*)(m + (size_t)grow1 * BN + gcol) =
                    __floats2half2_rn(c[i][j][2] * s1, c[i][j][3] * s1);
        }
    }
}

// ---------------------------------------------------------------------------
// Gathers: pure row sums of pre-scaled fp16 messages, 16B loads.
// gather1: half-warp (16 lanes) per node, 8 halves per lane.
// gather2: 8 lanes per node, 8 halves per lane.
// ---------------------------------------------------------------------------
__global__ __launch_bounds__(256)
void gather1_kernel(const __half* __restrict__ m1, float* __restrict__ h1,
                    const int* __restrict__ row_ptr, const int* __restrict__ eidx,
                    const float* __restrict__ dis, const float* __restrict__ b1)
{
    int n = blockIdx.x * 16 + (threadIdx.x >> 4);
    if (n >= NN) return;
    int lane = threadIdx.x & 15;              // halves [lane*8, lane*8+8)

    int start = row_ptr[n];
    int end   = row_ptr[n + 1];

    float acc[8];
#pragma unroll
    for (int k = 0; k < 8; k++) acc[k] = 0.f;
    h8_acc(*(const uint4*)(m1 + (size_t)n * 128 + lane * 8), acc);   // self loop

    int e = start;
    for (; e + 8 <= end; e += 8) {
        uint4 v[8];
#pragma unroll
        for (int q = 0; q < 8; q++) {
            int s = __ldg(eidx + e + q);
            v[q] = *(const uint4*)(m1 + (size_t)s * 128 + lane * 8);
        }
#pragma unroll
        for (int q = 0; q < 8; q++) h8_acc(v[q], acc);
    }
    for (; e < end; e++) {
        int s = __ldg(eidx + e);
        h8_acc(*(const uint4*)(m1 + (size_t)s * 128 + lane * 8), acc);
    }

    float dn = dis[n];
    float4 ba = *(const float4*)(b1 + lane * 8);
    float4 bb = *(const float4*)(b1 + lane * 8 + 4);
    float4 o0, o1;
    o0.x = fmaxf(fmaf(acc[0], dn, ba.x), 0.f);
    o0.y = fmaxf(fmaf(acc[1], dn, ba.y), 0.f);
    o0.z = fmaxf(fmaf(acc[2], dn, ba.z), 0.f);
    o0.w = fmaxf(fmaf(acc[3], dn, ba.w), 0.f);
    o1.x = fmaxf(fmaf(acc[4], dn, bb.x), 0.f);
    o1.y = fmaxf(fmaf(acc[5], dn, bb.y), 0.f);
    o1.z = fmaxf(fmaf(acc[6], dn, bb.z), 0.f);
    o1.w = fmaxf(fmaf(acc[7], dn, bb.w), 0.f);
    *(float4*)(h1 + (size_t)n * 128 + lane * 8)     = o0;
    *(float4*)(h1 + (size_t)n * 128 + lane * 8 + 4) = o1;
}

__global__ __launch_bounds__(256)
void gather2_kernel(const __half* __restrict__ m2, float* __restrict__ out,
                    const int* __restrict__ row_ptr, const int* __restrict__ eidx,
                    const float* __restrict__ dis, const float* __restrict__ b2)
{
    int n = blockIdx.x * 32 + (threadIdx.x >> 3);
    if (n >= NN) return;
    int lane = threadIdx.x & 7;               // halves [lane*8, lane*8+8)

    int start = row_ptr[n];
    int end   = row_ptr[n + 1];

    float acc[8];
#pragma unroll
    for (int k = 0; k < 8; k++) acc[k] = 0.f;
    h8_acc(*(const uint4*)(m2 + (size_t)n * 64 + lane * 8), acc);    // self loop

    int e = start;
    for (; e + 8 <= end; e += 8) {
        uint4 v[8];
#pragma unroll
        for (int q = 0; q < 8; q++) {
            int s = __ldg(eidx + e + q);
            v[q] = *(const uint4*)(m2 + (size_t)s * 64 + lane * 8);
        }
#pragma unroll
        for (int q = 0; q < 8; q++) h8_acc(v[q], acc);
    }
    for (; e < end; e++) {
        int s = __ldg(eidx + e);
        h8_acc(*(const uint4*)(m2 + (size_t)s * 64 + lane * 8), acc);
    }

    float dn = dis[n];
    float4 ba = *(const float4*)(b2 + lane * 8);
    float4 bb = *(const float4*)(b2 + lane * 8 + 4);
    float4 o0, o1;
    o0.x = fmaf(acc[0], dn, ba.x);
    o0.y = fmaf(acc[1], dn, ba.y);
    o0.z = fmaf(acc[2], dn, ba.z);
    o0.w = fmaf(acc[3], dn, ba.w);
    o1.x = fmaf(acc[4], dn, bb.x);
    o1.y = fmaf(acc[5], dn, bb.y);
    o1.z = fmaf(acc[6], dn, bb.z);
    o1.w = fmaf(acc[7], dn, bb.w);
    *(float4*)(out + (size_t)n * 64 + lane * 8)     = o0;
    *(float4*)(out + (size_t)n * 64 + lane * 8 + 4) = o1;
}

// ---------------------------------------------------------------------------
extern "C" void kernel_launch(void* const* d_in, const int* in_sizes, int n_in,
                              void* d_out, int out_size)
{
    void *pv;
    cudaGetSymbolAddress(&pv, g_hist);    int*    hist    = (int*)pv;
    cudaGetSymbolAddress(&pv, g_row_ptr); int*    row_ptr = (int*)pv;
    cudaGetSymbolAddress(&pv, g_cursor);  int*    cursor  = (int*)pv;
    cudaGetSymbolAddress(&pv, g_part);    int*    part    = (int*)pv;
    cudaGetSymbolAddress(&pv, g_eidx);    int*    eidx    = (int*)pv;
    cudaGetSymbolAddress(&pv, g_dis);     float*  dis     = (float*)pv;
    cudaGetSymbolAddress(&pv, g_m1h);     __half* m1      = (__half*)pv;
    cudaGetSymbolAddress(&pv, g_h1);      float*  h1      = (float*)pv;
    cudaGetSymbolAddress(&pv, g_m2h);     __half* m2      = (__half*)pv;
    cudaGetSymbolAddress(&pv, g_w1r);     float*  w1r     = (float*)pv;
    cudaGetSymbolAddress(&pv, g_w2r);     float*  w2r     = (float*)pv;

    const long long elems[6] = {38400000LL, 49152LL, 128LL, 8192LL, 64LL, 6400000LL};
    const long long bytesz[6] = {38400000LL*4, 49152LL*4, 128LL*4, 8192LL*4, 64LL*4, 6400000LL*4};
    const void* ptr[6] = {nullptr,nullptr,nullptr,nullptr,nullptr,nullptr};

    int matched = 0;
    for (int i = 0; i < n_in && i < 16; i++)
        for (int j = 0; j < 6; j++)
            if ((long long)in_sizes[i] == elems[j] && !ptr[j]) { ptr[j] = d_in[i]; matched++; break; }
    if (matched < 6) {
        for (int j = 0; j < 6; j++) ptr[j] = nullptr;
        matched = 0;
        for (int i = 0; i < n_in && i < 16; i++)
            for (int j = 0; j < 6; j++)
                if ((long long)in_sizes[i] == bytesz[j] && !ptr[j]) { ptr[j] = d_in[i]; matched++; break; }
    }
    if (matched < 6 && n_in >= 6)
        for (int j = 0; j < 6; j++) ptr[j] = d_in[j];

    const float* x  = (const float*)ptr[0];
    const float* W1 = (const float*)ptr[1];
    const float* b1 = (const float*)ptr[2];
    const float* W2 = (const float*)ptr[3];
    const float* b2 = (const float*)ptr[4];
    const int*   ei = (const int*)  ptr[5];
    const int* src = ei;
    const int* dst = ei + EE;
    float* out = (float*)d_out;

    const int smem1 = 4 * (128 * 20 + 16 * 136) * 4;   // 75776 B
    const int smem2 = 4 * (128 * 20 + 16 * 72) * 4;    // 59392 B
    cudaFuncSetAttribute(gemm_tf32_async<128>,
                         cudaFuncAttributeMaxDynamicSharedMemorySize, smem1);
    cudaFuncSetAttribute(gemm_tf32_async<64>,
                         cudaFuncAttributeMaxDynamicSharedMemorySize, smem2);

    const bool fork = (g_side && g_ev_fork && g_ev_join);
    cudaStream_t s_csr = fork ? g_side : (cudaStream_t)0;

    if (fork) {
        cudaEventRecord(g_ev_fork, 0);
        cudaStreamWaitEvent(g_side, g_ev_fork, 0);
    }

    // CSR on side stream; gemm1 is the 4th launch (profiler slot).
    zero_hist_kernel<<<(NN + 255) / 256, 256, 0, s_csr>>>(hist);
    hist_kernel     <<<(EE + 255) / 256, 256, 0, s_csr>>>(dst, hist);

    round_w_kernel<<<(384 * 128 + 255) / 256, 256>>>(W1, W2, w1r, w2r);
    gemm_tf32_async<128><<<(NN + 127) / 128, 256, smem1>>>(x, w1r, m1, nullptr, NN, 384);

    scan1_kernel    <<<SCAN_BLOCKS, 1024, 0, s_csr>>>(hist, row_ptr, part);
    scan2_kernel    <<<1, 128, 0, s_csr>>>(part, row_ptr);
    scan3_kernel    <<<SCAN_BLOCKS, 1024, 0, s_csr>>>(row_ptr, part, hist, cursor, dis);
    place_kernel    <<<(EE + 255) / 256, 256, 0, s_csr>>>(src, dst, cursor, eidx);
    if (fork) cudaEventRecord(g_ev_join, g_side);

    if (fork) cudaStreamWaitEvent((cudaStream_t)0, g_ev_join, 0);

    // msg1 = dis * m1 (in place), then pure-sum gathers.
    scale_m1_kernel<<<(NN * 32 + 255) / 256, 256>>>(m1, dis);
    gather1_kernel<<<(NN + 15) / 16, 256>>>(m1, h1, row_ptr, eidx, dis, b1);

    // gemm2 folds dis into epilogue: msg2 = dis * (h1 @ W2).
    gemm_tf32_async<64><<<(NN + 127) / 128, 256, smem2>>>(h1, w2r, m2, dis, NN, 128);

    gather2_kernel<<<(NN + 31) / 32, 256>>>(m2, out, row_ptr, eidx, dis, b2);
}